// round 5
// baseline (speedup 1.0000x reference)
#include <cuda_runtime.h>
#include <math.h>

// ---------------- problem constants ----------------
#define NNODES 1000000
#define MEMD   172
#define MSGD   100
#define EDD    100
#define KN     10
#define BE     32768      // batch of edges
#define NB2    65536      // 2*BE nodes
#define NBRROWS 655360    // 2*BE*KN
#define HIDD   128
#define XD     444        // 172+172+100
#define GD     516        // 3*172

// ---------------- device scratch (no cudaMalloc allowed) ----------------
__device__ float g_X[BE * XD];
__device__ float g_H1[BE * MSGD];
__device__ float g_RAW[BE * MSGD];
__device__ float g_GI[BE * GD];
__device__ float g_GH[NB2 * GD];          // rows [0,BE)=src side, [BE,2BE)=dst side
__device__ float g_newmem[NB2 * MEMD];
__device__ int   g_upd[NNODES];           // 0 = untouched, else winner_index+1
__device__ int   g_nridx[NBRROWS];        // resolved gather index for neighbor rows
__device__ int   g_nodeidx[NB2];          // resolved gather index for node rows
__device__ float g_Q[NB2 * EDD];
__device__ float g_KV[NBRROWS * 200];     // [kh(100) | vh(100)]
__device__ float g_AO[NB2 * EDD];
__device__ float g_Z[NB2 * MSGD];
__device__ float g_H1F[BE * HIDD];
__device__ float g_CWkv[200 * 272];       // fused (Wk@k_W ; Wv@v_W)
__device__ float g_CWq[100 * 172];        // fused Wq@q_W
__device__ float g_CWc[100 * 272];        // c_W with o_W folded into last 100 cols
__device__ float g_cb[400];               // [0,200) kv bias, [200,300) q bias, [300,400) c bias

// ---------------- helpers ----------------
__device__ __forceinline__ float sigm(float x) { return 1.f / (1.f + expf(-x)); }

__device__ __forceinline__ unsigned long long packdup(float x) {
    unsigned long long v;
    asm("mov.b64 %0, {%1, %1};" : "=l"(v) : "r"(__float_as_uint(x)));
    return v;
}
__device__ __forceinline__ void fma2(unsigned long long& d, unsigned long long a,
                                     unsigned long long b) {
    asm("fma.rn.f32x2 %0, %1, %2, %0;" : "+l"(d) : "l"(a), "l"(b));
}
__device__ __forceinline__ void unpack2(unsigned long long v, float& lo, float& hi) {
    unsigned int a, b;
    asm("mov.b64 {%0, %1}, %2;" : "=r"(a), "=r"(b) : "l"(v));
    lo = __uint_as_float(a); hi = __uint_as_float(b);
}

// ---------------- weight combination kernels (tiny) ----------------
__global__ void cw_kv_kernel(const float* __restrict__ inW,
                             const float* __restrict__ kW,
                             const float* __restrict__ vW)
{
    int idx = blockIdx.x * blockDim.x + threadIdx.x;
    if (idx >= 200 * 272) return;
    int o = idx / 272, i = idx - o * 272;
    const float* Wrow = inW + (100 + o) * 100;      // o<100 -> Wk rows, o>=100 -> Wv rows
    const float* Msel = (o < 100) ? kW : vW;
    float s = 0.f;
    for (int j = 0; j < 100; j++) s += Wrow[j] * Msel[j * 272 + i];
    g_CWkv[idx] = s;
}

__global__ void cw_q_kernel(const float* __restrict__ inW,
                            const float* __restrict__ qW)
{
    int idx = blockIdx.x * blockDim.x + threadIdx.x;
    if (idx >= 100 * 172) return;
    int o = idx / 172, i = idx - o * 172;
    const float* Wrow = inW + o * 100;              // Wq rows [0,100)
    float s = 0.f;
    for (int j = 0; j < 100; j++) s += Wrow[j] * qW[j * 172 + i];
    g_CWq[idx] = s;
}

__global__ void cw_c_kernel(const float* __restrict__ cW,
                            const float* __restrict__ oW)
{
    int idx = blockIdx.x * blockDim.x + threadIdx.x;
    if (idx >= 100 * 272) return;
    int o = idx / 272, i = idx - o * 272;
    if (i < 172) {
        g_CWc[idx] = cW[o * 272 + i];
    } else {
        int c2 = i - 172;
        float s = 0.f;
        for (int d = 0; d < 100; d++) s += cW[o * 272 + 172 + d] * oW[d * 100 + c2];
        g_CWc[idx] = s;
    }
}

__global__ void cb_kernel(const float* __restrict__ inW, const float* __restrict__ inB,
                          const float* __restrict__ kb,  const float* __restrict__ vb,
                          const float* __restrict__ qb,
                          const float* __restrict__ cW,  const float* __restrict__ cb_,
                          const float* __restrict__ ob)
{
    int t = threadIdx.x;
    if (t < 200) {
        int o = t;
        const float* Wrow = inW + (100 + o) * 100;
        const float* bsel = (o < 100) ? kb : vb;
        float s = inB[100 + o];
        for (int j = 0; j < 100; j++) s += Wrow[j] * bsel[j];
        g_cb[t] = s;
    } else if (t < 300) {
        int o = t - 200;
        const float* Wrow = inW + o * 100;
        float s = inB[o];
        for (int j = 0; j < 100; j++) s += Wrow[j] * qb[j];
        g_cb[t] = s;
    } else if (t < 400) {
        int o = t - 300;
        float s = cb_[o];
        for (int d = 0; d < 100; d++) s += cW[o * 272 + 172 + d] * ob[d];
        g_cb[t] = s;
    }
}

// ---------------- prep: X = [mem[src] | mem[dst] | sin(dt*tw+tb)] ----------------
__global__ void prepx_kernel(const float* __restrict__ mem,
                             const int* __restrict__ src, const int* __restrict__ dst,
                             const float* __restrict__ dt,
                             const float* __restrict__ tw, const float* __restrict__ tb)
{
    int b = blockIdx.x, t = threadIdx.x;           // 128 threads
    float4* xr = reinterpret_cast<float4*>(g_X + (size_t)b * XD);
    for (int q = t; q < 111; q += 128) {           // 43 + 43 + 25 float4 chunks
        float4 v;
        if (q < 43) {
            v = *reinterpret_cast<const float4*>(mem + (size_t)src[b] * MEMD + q * 4);
        } else if (q < 86) {
            v = *reinterpret_cast<const float4*>(mem + (size_t)dst[b] * MEMD + (q - 43) * 4);
        } else {
            int j = (q - 86) * 4;
            float d = dt[b];
            v = make_float4(__sinf(d * tw[j]     + tb[j]),
                            __sinf(d * tw[j + 1] + tb[j + 1]),
                            __sinf(d * tw[j + 2] + tb[j + 2]),
                            __sinf(d * tw[j + 3] + tb[j + 3]));
        }
        xr[q] = v;
    }
}

// ---------------- A-operand loaders (float4, c always multiple of 4) ----------------
struct DenseLd {
    const float* A; int lda; int off;
    __device__ __forceinline__ float4 ld4(int r, int c) const {
        return *reinterpret_cast<const float4*>(A + (size_t)r * lda + off + c);
    }
};
struct GHLd {   // rows [0,BE): X cols [0,172); rows [BE,2BE): X cols [172,344)
    const float* X;
    __device__ __forceinline__ float4 ld4(int r, int c) const {
        int rr = (r < BE) ? r : r - BE;
        int off = (r < BE) ? 0 : 172;
        return *reinterpret_cast<const float4*>(X + (size_t)rr * XD + off + c);
    }
};
struct NodeLd {
    const float* mem; const float* nmem; const int* idx;
    __device__ __forceinline__ float4 ld4(int r, int c) const {
        int i = idx[r];
        const float* p = (i >= 0) ? mem + (size_t)i * MEMD
                                  : nmem + (size_t)(-i - 1) * MEMD;
        return *reinterpret_cast<const float4*>(p + c);
    }
};
struct NbrLd {
    const float* mem; const float* nmem; const int* idx;
    const float* ndt; const float* tw; const float* tb;
    __device__ __forceinline__ float4 ld4(int r, int c) const {
        if (c < MEMD) {
            int i = idx[r];
            const float* p = (i >= 0) ? mem + (size_t)i * MEMD
                                      : nmem + (size_t)(-i - 1) * MEMD;
            return *reinterpret_cast<const float4*>(p + c);
        }
        int j = c - MEMD;
        float d = ndt[r];
        return make_float4(__sinf(d * tw[j]     + tb[j]),
                           __sinf(d * tw[j + 1] + tb[j + 1]),
                           __sinf(d * tw[j + 2] + tb[j + 2]),
                           __sinf(d * tw[j + 3] + tb[j + 3]));
    }
};
struct NodeAOLd {
    NodeLd nl; const float* ao;
    __device__ __forceinline__ float4 ld4(int r, int c) const {
        if (c < MEMD) return nl.ld4(r, c);
        return *reinterpret_cast<const float4*>(ao + (size_t)r * EDD + (c - MEMD));
    }
};
struct ZPairLd {
    const float* Z;
    __device__ __forceinline__ float4 ld4(int r, int c) const {
        if (c < 100) return *reinterpret_cast<const float4*>(Z + (size_t)r * 100 + c);
        return *reinterpret_cast<const float4*>(Z + (size_t)(r + BE) * 100 + (c - 100));
    }
};

// ---------------- generic fused-gather SGEMM, double-buffered ----------------
// C[M,O] = act(A[M,I] @ W[O,I]^T + bias); M % 64 == 0, I % 4 == 0, O % 4 == 0.
// 64x128 tile, BK=16, 256 threads, 4x8 per-thread register tile, packed f32x2 FMA.
// Software pipeline: prefetch tile s+1 into registers while computing tile s.
constexpr int BMT = 64, BNT = 128, BKT = 16;

template <class L>
__global__ __launch_bounds__(256, 2)
void gemm_kernel(L ld, const float* __restrict__ W, const float* __restrict__ bias,
                 float* __restrict__ C, int M, int I, int O, int relu)
{
    __shared__ __align__(16) float As[2][BKT][BMT + 4];   // 68 floats/row (272B, 16B mult)
    __shared__ __align__(16) float Bs[2][BKT][BNT + 4];   // 132 floats/row (528B, 16B mult)
    const int t  = threadIdx.x;
    const int tx = t & 15, ty = t >> 4;                   // 16 x 16 thread grid
    const int bm = blockIdx.x * BMT, bn = blockIdx.y * BNT;
    // A load map: 256 threads x one float4 = 64 rows x 16 cols
    const int ar = t >> 2, ac = (t & 3) * 4;
    // B load map: 256 threads x two float4 = 128 rows x 16 cols
    const int br = t >> 1, bc = (t & 1) * 8;
    const bool bvalid = (bn + br) < O;
    const float* wrow = W + (size_t)(bn + br) * I + bc;

    unsigned long long acc2[4][4];                        // 4 rows x 4 col-pairs (8 cols)
#pragma unroll
    for (int i = 0; i < 4; i++)
#pragma unroll
        for (int j = 0; j < 4; j++) acc2[i][j] = 0ULL;

    const int steps = (I + BKT - 1) / BKT;

    float4 pa, pb0, pb1;
    // --- prologue: fetch tile 0 ---
    {
        pa = make_float4(0.f, 0.f, 0.f, 0.f);
        if (ac < I) pa = ld.ld4(bm + ar, ac);
        pb0 = make_float4(0.f, 0.f, 0.f, 0.f); pb1 = pb0;
        if (bvalid) {
            if (bc + 3 < I) pb0 = *reinterpret_cast<const float4*>(wrow);
            if (bc + 7 < I) pb1 = *reinterpret_cast<const float4*>(wrow + 4);
        }
        As[0][ac + 0][ar] = pa.x; As[0][ac + 1][ar] = pa.y;
        As[0][ac + 2][ar] = pa.z; As[0][ac + 3][ar] = pa.w;
        Bs[0][bc + 0][br] = pb0.x; Bs[0][bc + 1][br] = pb0.y;
        Bs[0][bc + 2][br] = pb0.z; Bs[0][bc + 3][br] = pb0.w;
        Bs[0][bc + 4][br] = pb1.x; Bs[0][bc + 5][br] = pb1.y;
        Bs[0][bc + 6][br] = pb1.z; Bs[0][bc + 7][br] = pb1.w;
    }
    __syncthreads();

    for (int s = 0; s < steps; s++) {
        const int buf = s & 1;
        const bool more = (s + 1) < steps;
        // --- prefetch tile s+1 into registers ---
        if (more) {
            const int k0 = (s + 1) * BKT;
            pa = make_float4(0.f, 0.f, 0.f, 0.f);
            if (k0 + ac < I) pa = ld.ld4(bm + ar, k0 + ac);
            pb0 = make_float4(0.f, 0.f, 0.f, 0.f); pb1 = pb0;
            if (bvalid) {
                if (k0 + bc + 3 < I) pb0 = *reinterpret_cast<const float4*>(wrow + k0);
                if (k0 + bc + 7 < I) pb1 = *reinterpret_cast<const float4*>(wrow + k0 + 4);
            }
        }
        // --- compute tile s from SMEM[buf] ---
#pragma unroll
        for (int kk = 0; kk < BKT; kk++) {
            float4 a4 = *reinterpret_cast<const float4*>(&As[buf][kk][ty * 4]);
            ulonglong2 q0 = *reinterpret_cast<const ulonglong2*>(&Bs[buf][kk][tx * 8]);
            ulonglong2 q1 = *reinterpret_cast<const ulonglong2*>(&Bs[buf][kk][tx * 8 + 4]);
            unsigned long long ap;
            ap = packdup(a4.x);
            fma2(acc2[0][0], ap, q0.x); fma2(acc2[0][1], ap, q0.y);
            fma2(acc2[0][2], ap, q1.x); fma2(acc2[0][3], ap, q1.y);
            ap = packdup(a4.y);
            fma2(acc2[1][0], ap, q0.x); fma2(acc2[1][1], ap, q0.y);
            fma2(acc2[1][2], ap, q1.x); fma2(acc2[1][3], ap, q1.y);
            ap = packdup(a4.z);
            fma2(acc2[2][0], ap, q0.x); fma2(acc2[2][1], ap, q0.y);
            fma2(acc2[2][2], ap, q1.x); fma2(acc2[2][3], ap, q1.y);
            ap = packdup(a4.w);
            fma2(acc2[3][0], ap, q0.x); fma2(acc2[3][1], ap, q0.y);
            fma2(acc2[3][2], ap, q1.x); fma2(acc2[3][3], ap, q1.y);
        }
        // --- store prefetched tile into SMEM[buf^1] ---
        if (more) {
            const int nb = buf ^ 1;
            As[nb][ac + 0][ar] = pa.x; As[nb][ac + 1][ar] = pa.y;
            As[nb][ac + 2][ar] = pa.z; As[nb][ac + 3][ar] = pa.w;
            Bs[nb][bc + 0][br] = pb0.x; Bs[nb][bc + 1][br] = pb0.y;
            Bs[nb][bc + 2][br] = pb0.z; Bs[nb][bc + 3][br] = pb0.w;
            Bs[nb][bc + 4][br] = pb1.x; Bs[nb][bc + 5][br] = pb1.y;
            Bs[nb][bc + 6][br] = pb1.z; Bs[nb][bc + 7][br] = pb1.w;
            __syncthreads();
        }
    }

#pragma unroll
    for (int i = 0; i < 4; i++) {
        int row = bm + ty * 4 + i;                        // M % 64 == 0, always valid
        float* crow = C + (size_t)row * O;
#pragma unroll
        for (int g = 0; g < 2; g++) {
            int col = bn + tx * 8 + g * 4;
            if (col < O) {                                // O % 4 == 0 -> group all-or-none
                float x0, x1, x2, x3;
                unpack2(acc2[i][g * 2 + 0], x0, x1);
                unpack2(acc2[i][g * 2 + 1], x2, x3);
                float4 v = make_float4(x0 + bias[col], x1 + bias[col + 1],
                                       x2 + bias[col + 2], x3 + bias[col + 3]);
                if (relu) {
                    v.x = fmaxf(v.x, 0.f); v.y = fmaxf(v.y, 0.f);
                    v.z = fmaxf(v.z, 0.f); v.w = fmaxf(v.w, 0.f);
                }
                *reinterpret_cast<float4*>(crow + col) = v;
            }
        }
    }
}

// ---------------- GRU combine ----------------
__global__ void gru_kernel()
{
    int idx = blockIdx.x * blockDim.x + threadIdx.x;
    if (idx >= BE * MEMD) return;
    int b = idx / MEMD, j = idx - b * MEMD;
    const float* gi = g_GI + (size_t)b * GD;
    float ir = gi[j], iz = gi[172 + j], inn = gi[344 + j];
    {
        const float* gh = g_GH + (size_t)b * GD;
        float h = g_X[(size_t)b * XD + j];
        float r = sigm(ir + gh[j]);
        float z = sigm(iz + gh[172 + j]);
        float n = tanhf(inn + r * gh[344 + j]);
        g_newmem[(size_t)b * MEMD + j] = (1.f - z) * n + z * h;
    }
    {
        const float* gh = g_GH + (size_t)(BE + b) * GD;
        float h = g_X[(size_t)b * XD + 172 + j];
        float r = sigm(ir + gh[j]);
        float z = sigm(iz + gh[172 + j]);
        float n = tanhf(inn + r * gh[344 + j]);
        g_newmem[(size_t)(BE + b) * MEMD + j] = (1.f - z) * n + z * h;
    }
}

// ---------------- scatter priority (last-index-wins: dst over src, high idx wins) ----------------
__global__ void scatter_kernel(const int* __restrict__ src, const int* __restrict__ dst)
{
    int i = blockIdx.x * blockDim.x + threadIdx.x;
    if (i >= NB2) return;
    int node = (i < BE) ? src[i] : dst[i - BE];
    atomicMax(&g_upd[node], i + 1);
}

__global__ void clean_kernel(const int* __restrict__ src, const int* __restrict__ dst)
{
    int i = blockIdx.x * blockDim.x + threadIdx.x;
    if (i >= NB2) return;
    int node = (i < BE) ? src[i] : dst[i - BE];
    g_upd[node] = 0;
}

// ---------------- resolve gather indices once (pulls upd[] out of GEMM hot loop) ----------------
__global__ void resolve_nbr_kernel(const int* __restrict__ nid)
{
    int r = blockIdx.x * blockDim.x + threadIdx.x;
    if (r >= NBRROWS) return;
    int node = nid[r];
    int u = g_upd[node];
    g_nridx[r] = (u > 0) ? -u : node;     // negative -> g_newmem row (-v-1)
}

__global__ void resolve_node_kernel(const int* __restrict__ src, const int* __restrict__ dst)
{
    int i = blockIdx.x * blockDim.x + threadIdx.x;
    if (i >= NB2) return;
    int node = (i < BE) ? src[i] : dst[i - BE];
    int u = g_upd[node];
    g_nodeidx[i] = (u > 0) ? -u : node;
}

// ---------------- attention (2 heads x 10 neighbors) -> raw AO (o_W folded downstream) --------
__global__ void attn_kernel(const float* __restrict__ Q, const float* __restrict__ KV,
                            float* __restrict__ AO)
{
    int m = blockIdx.x;
    __shared__ float qs[EDD];
    __shared__ float att[2][KN];
    int t = threadIdx.x;
    if (t < EDD) qs[t] = Q[(size_t)m * EDD + t];
    __syncthreads();
    if (t < 2 * KN) {
        int h = t / KN, k = t - h * KN;
        const float* kr = KV + (size_t)(m * KN + k) * 200 + h * 50;
        const float* qh = qs + h * 50;
        float s = 0.f;
#pragma unroll 10
        for (int j = 0; j < 50; j++) s += qh[j] * kr[j];
        att[h][k] = s * 0.14142135623730951f;   // 1/sqrt(50)
    }
    __syncthreads();
    if (t < 2) {
        float mx = -1e30f;
        for (int k = 0; k < KN; k++) mx = fmaxf(mx, att[t][k]);
        float e[KN]; float sum = 0.f;
        for (int k = 0; k < KN; k++) { e[k] = expf(att[t][k] - mx); sum += e[k]; }
        float inv = 1.f / sum;
        for (int k = 0; k < KN; k++) att[t][k] = e[k] * inv;
    }
    __syncthreads();
    if (t < EDD) {
        int h = t / 50;
        float s = 0.f;
#pragma unroll
        for (int k = 0; k < KN; k++)
            s += att[h][k] * KV[(size_t)(m * KN + k) * 200 + 100 + t];
        AO[(size_t)m * EDD + t] = s;
    }
}

// ---------------- final score ----------------
__global__ void score_kernel(const float* __restrict__ H1F, const float* __restrict__ pW2,
                             const float* __restrict__ pb2, float* __restrict__ out)
{
    int warp = (blockIdx.x * blockDim.x + threadIdx.x) >> 5;
    int lane = threadIdx.x & 31;
    if (warp >= BE) return;
    const float* h = H1F + (size_t)warp * HIDD;
    float s = 0.f;
#pragma unroll
    for (int j = lane; j < HIDD; j += 32) s += h[j] * pW2[j];
#pragma unroll
    for (int o = 16; o > 0; o >>= 1) s += __shfl_xor_sync(0xffffffffu, s, o);
    if (lane == 0) out[warp] = 1.f / (1.f + expf(-(s + pb2[0])));
}

// ---------------- host-side ----------------
template <class L>
static void run_gemm(const L& ld, const float* W, const float* b, float* C,
                     int M, int I, int O, int relu)
{
    dim3 grid(M / BMT, (O + BNT - 1) / BNT);
    gemm_kernel<L><<<grid, 256>>>(ld, W, b, C, M, I, O, relu);
}

extern "C" void kernel_launch(void* const* d_in, const int* in_sizes, int n_in,
                              void* d_out, int out_size)
{
    (void)in_sizes; (void)n_in; (void)out_size;
    const float* memory  = (const float*)d_in[0];
    const int*   src     = (const int*)  d_in[1];
    const int*   dst     = (const int*)  d_in[2];
    const float* dt      = (const float*)d_in[3];
    const int*   nids    = (const int*)  d_in[4];
    const float* ndt     = (const float*)d_in[5];
    const float* t_w     = (const float*)d_in[6];
    const float* t_b     = (const float*)d_in[7];
    const float* m_W1    = (const float*)d_in[8];
    const float* m_b1    = (const float*)d_in[9];
    const float* m_W2    = (const float*)d_in[10];
    const float* m_b2    = (const float*)d_in[11];
    const float* g_Wih   = (const float*)d_in[12];
    const float* g_Whh   = (const float*)d_in[13];
    const float* g_bih   = (const float*)d_in[14];
    const float* g_bhh   = (const float*)d_in[15];
    const float* k_W     = (const float*)d_in[16];
    const float* k_b     = (const float*)d_in[17];
    const float* v_W     = (const float*)d_in[18];
    const float* v_b     = (const float*)d_in[19];
    const float* q_W     = (const float*)d_in[20];
    const float* q_b     = (const float*)d_in[21];
    const float* in_W    = (const float*)d_in[22];
    const float* in_b    = (const float*)d_in[23];
    const float* o_W     = (const float*)d_in[24];
    const float* o_b     = (const float*)d_in[25];
    const float* c_W     = (const float*)d_in[26];
    const float* c_b     = (const float*)d_in[27];
    const float* p_W1    = (const float*)d_in[28];
    const float* p_b1    = (const float*)d_in[29];
    const float* p_W2    = (const float*)d_in[30];
    const float* p_b2    = (const float*)d_in[31];
    float* out = (float*)d_out;

    float *dX, *dH1, *dRAW, *dGI, *dGH, *dNM, *dQ, *dKV, *dAO, *dZ, *dH1F;
    float *dCWkv, *dCWq, *dCWc, *dcb;
    int *dUPD, *dNRI, *dNI;
    cudaGetSymbolAddress((void**)&dX,    g_X);
    cudaGetSymbolAddress((void**)&dH1,   g_H1);
    cudaGetSymbolAddress((void**)&dRAW,  g_RAW);
    cudaGetSymbolAddress((void**)&dGI,   g_GI);
    cudaGetSymbolAddress((void**)&dGH,   g_GH);
    cudaGetSymbolAddress((void**)&dNM,   g_newmem);
    cudaGetSymbolAddress((void**)&dUPD,  g_upd);
    cudaGetSymbolAddress((void**)&dNRI,  g_nridx);
    cudaGetSymbolAddress((void**)&dNI,   g_nodeidx);
    cudaGetSymbolAddress((void**)&dQ,    g_Q);
    cudaGetSymbolAddress((void**)&dKV,   g_KV);
    cudaGetSymbolAddress((void**)&dAO,   g_AO);
    cudaGetSymbolAddress((void**)&dZ,    g_Z);
    cudaGetSymbolAddress((void**)&dH1F,  g_H1F);
    cudaGetSymbolAddress((void**)&dCWkv, g_CWkv);
    cudaGetSymbolAddress((void**)&dCWq,  g_CWq);
    cudaGetSymbolAddress((void**)&dCWc,  g_CWc);
    cudaGetSymbolAddress((void**)&dcb,   g_cb);

    // 1) fused weight precompute
    cw_kv_kernel<<<(200 * 272 + 255) / 256, 256>>>(in_W, k_W, v_W);
    cw_q_kernel <<<(100 * 172 + 255) / 256, 256>>>(in_W, q_W);
    cw_c_kernel <<<(100 * 272 + 255) / 256, 256>>>(c_W, o_W);
    cb_kernel   <<<1, 512>>>(in_W, in_b, k_b, v_b, q_b, c_W, c_b, o_b);

    // 2) X = [s_src | s_dst | time_enc(dt)]
    prepx_kernel<<<BE, 128>>>(memory, src, dst, dt, t_w, t_b);

    // 3) message MLP
    run_gemm(DenseLd{dX, XD, 0},    m_W1, m_b1, dH1,  BE, XD,   MSGD, 1);
    run_gemm(DenseLd{dH1, MSGD, 0}, m_W2, m_b2, dRAW, BE, MSGD, MSGD, 0);

    // 4) GRU gates: gi (shared) + gh (src/dst fused into one M=2B GEMM)
    run_gemm(DenseLd{dRAW, MSGD, 0}, g_Wih, g_bih, dGI, BE,  MSGD, GD, 0);
    run_gemm(GHLd{dX},               g_Whh, g_bhh, dGH, NB2, MEMD, GD, 0);
    gru_kernel<<<(BE * MEMD + 255) / 256, 256>>>();

    // 5) scatter winners + resolve gather indices once
    scatter_kernel<<<NB2 / 256, 256>>>(src, dst);
    resolve_nbr_kernel <<<NBRROWS / 256, 256>>>(nids);
    resolve_node_kernel<<<NB2 / 256, 256>>>(src, dst);

    // 6) attention projections on updated memory (fused in_W weights)
    NodeLd nodeld{memory, dNM, dNI};
    run_gemm(nodeld, dCWq, dcb + 200, dQ, NB2, MEMD, EDD, 0);
    run_gemm(NbrLd{memory, dNM, dNRI, ndt, t_w, t_b},
             dCWkv, dcb, dKV, NBRROWS, 272, 200, 0);

    // 7) softmax attention
    attn_kernel<<<NB2, 128>>>(dQ, dKV, dAO);

    // 8) z = relu([node_mem | ao_raw] @ CWc^T + cbc)   (o_W folded)
    run_gemm(NodeAOLd{nodeld, dAO}, dCWc, dcb + 300, dZ, NB2, 272, MSGD, 1);

    // 9) link predictor
    run_gemm(ZPairLd{dZ}, p_W1, p_b1, dH1F, BE, 200, HIDD, 1);
    score_kernel<<<(BE * 32 + 255) / 256, 256>>>(dH1F, p_W2, p_b2, out);

    // 10) restore upd[] for deterministic graph replay
    clean_kernel<<<NB2 / 256, 256>>>(src, dst);
}

// round 8
// speedup vs baseline: 1.0250x; 1.0250x over previous
#include <cuda_runtime.h>
#include <math.h>

// ---------------- problem constants ----------------
#define NNODES 1000000
#define MEMD   172
#define MSGD   100
#define EDD    100
#define KN     10
#define BE     32768      // batch of edges
#define NB2    65536      // 2*BE nodes
#define NBRROWS 655360    // 2*BE*KN
#define HIDD   128
#define XD     444        // 172+172+100
#define GD     516        // 3*172

// ---------------- device scratch (no cudaMalloc allowed) ----------------
__device__ float g_X[BE * XD];
__device__ float g_H1[BE * MSGD];
__device__ float g_RAW[BE * MSGD];
__device__ float g_GI[BE * GD];
__device__ float g_GH[NB2 * GD];          // rows [0,BE)=src side, [BE,2BE)=dst side
__device__ float g_newmem[NB2 * MEMD];
__device__ int   g_upd[NNODES];           // 0 = untouched, else winner_index+1
__device__ int   g_nridx[NBRROWS];        // resolved gather index for neighbor rows
__device__ int   g_nodeidx[NB2];          // resolved gather index for node rows
__device__ float g_Q[NB2 * EDD];
__device__ float g_KV[NBRROWS * 200];     // [kh(100) | vh(100)]
__device__ float g_AO[NB2 * EDD];
__device__ float g_Z[NB2 * MSGD];
__device__ float g_H1F[BE * HIDD];
__device__ float g_CWkv[200 * 272];       // fused (Wk@k_W ; Wv@v_W)
__device__ float g_CWq[100 * 172];        // fused Wq@q_W
__device__ float g_CWc[100 * 272];        // c_W with o_W folded into last 100 cols
__device__ float g_cb[400];               // [0,200) kv bias, [200,300) q bias, [300,400) c bias

// ---------------- helpers ----------------
__device__ __forceinline__ float sigm(float x) { return 1.f / (1.f + expf(-x)); }

__device__ __forceinline__ unsigned long long packdup(float x) {
    unsigned long long v;
    asm("mov.b64 %0, {%1, %1};" : "=l"(v) : "r"(__float_as_uint(x)));
    return v;
}
__device__ __forceinline__ void fma2(unsigned long long& d, unsigned long long a,
                                     unsigned long long b) {
    asm("fma.rn.f32x2 %0, %1, %2, %0;" : "+l"(d) : "l"(a), "l"(b));
}
__device__ __forceinline__ void unpack2(unsigned long long v, float& lo, float& hi) {
    unsigned int a, b;
    asm("mov.b64 {%0, %1}, %2;" : "=r"(a), "=r"(b) : "l"(v));
    lo = __uint_as_float(a); hi = __uint_as_float(b);
}

// ---------------- merged weight-prep kernel (was 4 separate launches) ----------------
// work ranges: [0, 54400)        cw_kv  (200 x 272)
//              [54400, 71600)    cw_q   (100 x 172)
//              [71600, 98800)    cw_c   (100 x 272)
//              [98800, 99200)    cb     (400)
#define PREPW_TOTAL 99200
__global__ void prepw_kernel(const float* __restrict__ inW, const float* __restrict__ inB,
                             const float* __restrict__ kW,  const float* __restrict__ kb,
                             const float* __restrict__ vW,  const float* __restrict__ vb,
                             const float* __restrict__ qW,  const float* __restrict__ qb,
                             const float* __restrict__ cW,  const float* __restrict__ cb_,
                             const float* __restrict__ oW,  const float* __restrict__ ob)
{
    int idx = blockIdx.x * blockDim.x + threadIdx.x;
    if (idx < 54400) {
        int o = idx / 272, i = idx - o * 272;
        const float* Wrow = inW + (100 + o) * 100;      // o<100 -> Wk rows, o>=100 -> Wv rows
        const float* Msel = (o < 100) ? kW : vW;
        float s = 0.f;
        for (int j = 0; j < 100; j++) s += Wrow[j] * Msel[j * 272 + i];
        g_CWkv[idx] = s;
    } else if (idx < 71600) {
        int q = idx - 54400;
        int o = q / 172, i = q - o * 172;
        const float* Wrow = inW + o * 100;              // Wq rows [0,100)
        float s = 0.f;
        for (int j = 0; j < 100; j++) s += Wrow[j] * qW[j * 172 + i];
        g_CWq[q] = s;
    } else if (idx < 98800) {
        int q = idx - 71600;
        int o = q / 272, i = q - o * 272;
        if (i < 172) {
            g_CWc[q] = cW[o * 272 + i];
        } else {
            int c2 = i - 172;
            float s = 0.f;
            for (int d = 0; d < 100; d++) s += cW[o * 272 + 172 + d] * oW[d * 100 + c2];
            g_CWc[q] = s;
        }
    } else if (idx < PREPW_TOTAL) {
        int t = idx - 98800;
        if (t < 200) {
            int o = t;
            const float* Wrow = inW + (100 + o) * 100;
            const float* bsel = (o < 100) ? kb : vb;
            float s = inB[100 + o];
            for (int j = 0; j < 100; j++) s += Wrow[j] * bsel[j];
            g_cb[t] = s;
        } else if (t < 300) {
            int o = t - 200;
            const float* Wrow = inW + o * 100;
            float s = inB[o];
            for (int j = 0; j < 100; j++) s += Wrow[j] * qb[j];
            g_cb[t] = s;
        } else {
            int o = t - 300;
            float s = cb_[o];
            for (int d = 0; d < 100; d++) s += cW[o * 272 + 172 + d] * ob[d];
            g_cb[t] = s;
        }
    }
}

// ---------------- prep: X = [mem[src] | mem[dst] | sin(dt*tw+tb)] ----------------
__global__ void prepx_kernel(const float* __restrict__ mem,
                             const int* __restrict__ src, const int* __restrict__ dst,
                             const float* __restrict__ dt,
                             const float* __restrict__ tw, const float* __restrict__ tb)
{
    int b = blockIdx.x, t = threadIdx.x;           // 128 threads
    float4* xr = reinterpret_cast<float4*>(g_X + (size_t)b * XD);
    for (int q = t; q < 111; q += 128) {           // 43 + 43 + 25 float4 chunks
        float4 v;
        if (q < 43) {
            v = *reinterpret_cast<const float4*>(mem + (size_t)src[b] * MEMD + q * 4);
        } else if (q < 86) {
            v = *reinterpret_cast<const float4*>(mem + (size_t)dst[b] * MEMD + (q - 43) * 4);
        } else {
            int j = (q - 86) * 4;
            float d = dt[b];
            v = make_float4(__sinf(d * tw[j]     + tb[j]),
                            __sinf(d * tw[j + 1] + tb[j + 1]),
                            __sinf(d * tw[j + 2] + tb[j + 2]),
                            __sinf(d * tw[j + 3] + tb[j + 3]));
        }
        xr[q] = v;
    }
}

// ---------------- A-operand loaders: init(r) caches the resolved row once ----------------
struct DenseLd {
    const float* A; int lda; int off;
    const float* p;
    __device__ __forceinline__ void init(int r) { p = A + (size_t)r * lda + off; }
    __device__ __forceinline__ float4 ld4(int c) const {
        return *reinterpret_cast<const float4*>(p + c);
    }
};
struct GHLd {   // rows [0,BE): X cols [0,172); rows [BE,2BE): X cols [172,344)
    const float* X;
    const float* p;
    __device__ __forceinline__ void init(int r) {
        int rr  = (r < BE) ? r : r - BE;
        int off = (r < BE) ? 0 : 172;
        p = X + (size_t)rr * XD + off;
    }
    __device__ __forceinline__ float4 ld4(int c) const {
        return *reinterpret_cast<const float4*>(p + c);
    }
};
struct NodeLd {
    const float* mem; const float* nmem; const int* idx;
    const float* p;
    __device__ __forceinline__ void init(int r) {
        int i = idx[r];
        p = (i >= 0) ? mem + (size_t)i * MEMD : nmem + (size_t)(-i - 1) * MEMD;
    }
    __device__ __forceinline__ float4 ld4(int c) const {
        return *reinterpret_cast<const float4*>(p + c);
    }
};
struct NbrLd {
    const float* mem; const float* nmem; const int* idx;
    const float* ndt; const float* tw; const float* tb;
    const float* p; float d;
    __device__ __forceinline__ void init(int r) {
        int i = idx[r];
        p = (i >= 0) ? mem + (size_t)i * MEMD : nmem + (size_t)(-i - 1) * MEMD;
        d = ndt[r];
    }
    __device__ __forceinline__ float4 ld4(int c) const {
        if (c < MEMD) return *reinterpret_cast<const float4*>(p + c);
        int j = c - MEMD;
        return make_float4(__sinf(d * tw[j]     + tb[j]),
                           __sinf(d * tw[j + 1] + tb[j + 1]),
                           __sinf(d * tw[j + 2] + tb[j + 2]),
                           __sinf(d * tw[j + 3] + tb[j + 3]));
    }
};
struct NodeAOLd {
    NodeLd nl; const float* ao;
    const float* pao;
    __device__ __forceinline__ void init(int r) {
        nl.init(r);
        pao = ao + (size_t)r * EDD;
    }
    __device__ __forceinline__ float4 ld4(int c) const {
        if (c < MEMD) return nl.ld4(c);
        return *reinterpret_cast<const float4*>(pao + (c - MEMD));
    }
};
struct ZPairLd {
    const float* Z;
    const float* p0; const float* p1;
    __device__ __forceinline__ void init(int r) {
        p0 = Z + (size_t)r * 100;
        p1 = Z + (size_t)(r + BE) * 100;
    }
    __device__ __forceinline__ float4 ld4(int c) const {
        if (c < 100) return *reinterpret_cast<const float4*>(p0 + c);
        return *reinterpret_cast<const float4*>(p1 + (c - 100));
    }
};

// ---------------- generic fused-gather SGEMM, double-buffered ----------------
// C[M,O] = act(A[M,I] @ W[O,I]^T + bias); M % 64 == 0, I % 4 == 0, O % 4 == 0.
// 64x128 tile, BK=16, 256 threads, 4x8 per-thread register tile, packed f32x2 FMA.
constexpr int BMT = 64, BNT = 128, BKT = 16;

template <class L>
__global__ __launch_bounds__(256, 3)
void gemm_kernel(L ld, const float* __restrict__ W, const float* __restrict__ bias,
                 float* __restrict__ C, int M, int I, int O, int relu)
{
    __shared__ __align__(16) float As[2][BKT][BMT + 4];   // 68 floats/row (272B, 16B mult)
    __shared__ __align__(16) float Bs[2][BKT][BNT + 4];   // 132 floats/row (528B, 16B mult)
    const int t  = threadIdx.x;
    const int tx = t & 15, ty = t >> 4;                   // 16 x 16 thread grid
    const int bm = blockIdx.x * BMT, bn = blockIdx.y * BNT;
    // A load map: 256 threads x one float4 = 64 rows x 16 cols
    const int ar = t >> 2, ac = (t & 3) * 4;
    // B load map: 256 threads x two float4 = 128 rows x 16 cols
    const int br = t >> 1, bc = (t & 1) * 8;
    const bool bvalid = (bn + br) < O;
    const float* wrow = W + (size_t)(bn + br) * I + bc;

    ld.init(bm + ar);                                     // resolve gather row ONCE

    unsigned long long acc2[4][4];                        // 4 rows x 4 col-pairs (8 cols)
#pragma unroll
    for (int i = 0; i < 4; i++)
#pragma unroll
        for (int j = 0; j < 4; j++) acc2[i][j] = 0ULL;

    const int steps = (I + BKT - 1) / BKT;

    float4 pa, pb0, pb1;
    // --- prologue: fetch tile 0 ---
    {
        pa = make_float4(0.f, 0.f, 0.f, 0.f);
        if (ac < I) pa = ld.ld4(ac);
        pb0 = make_float4(0.f, 0.f, 0.f, 0.f); pb1 = pb0;
        if (bvalid) {
            if (bc + 3 < I) pb0 = *reinterpret_cast<const float4*>(wrow);
            if (bc + 7 < I) pb1 = *reinterpret_cast<const float4*>(wrow + 4);
        }
        As[0][ac + 0][ar] = pa.x; As[0][ac + 1][ar] = pa.y;
        As[0][ac + 2][ar] = pa.z; As[0][ac + 3][ar] = pa.w;
        Bs[0][bc + 0][br] = pb0.x; Bs[0][bc + 1][br] = pb0.y;
        Bs[0][bc + 2][br] = pb0.z; Bs[0][bc + 3][br] = pb0.w;
        Bs[0][bc + 4][br] = pb1.x; Bs[0][bc + 5][br] = pb1.y;
        Bs[0][bc + 6][br] = pb1.z; Bs[0][bc + 7][br] = pb1.w;
    }
    __syncthreads();

    for (int s = 0; s < steps; s++) {
        const int buf = s & 1;
        const bool more = (s + 1) < steps;
        // --- prefetch tile s+1 into registers ---
        if (more) {
            const int k0 = (s + 1) * BKT;
            pa = make_float4(0.f, 0.f, 0.f, 0.f);
            if (k0 + ac < I) pa = ld.ld4(k0 + ac);
            pb0 = make_float4(0.f, 0.f, 0.f, 0.f); pb1 = pb0;
            if (bvalid) {
                if (k0 + bc + 3 < I) pb0 = *reinterpret_cast<const float4*>(wrow + k0);
                if (k0 + bc + 7 < I) pb1 = *reinterpret_cast<const float4*>(wrow + k0 + 4);
            }
        }
        // --- compute tile s from SMEM[buf] ---
#pragma unroll
        for (int kk = 0; kk < BKT; kk++) {
            float4 a4 = *reinterpret_cast<const float4*>(&As[buf][kk][ty * 4]);
            ulonglong2 q0 = *reinterpret_cast<const ulonglong2*>(&Bs[buf][kk][tx * 8]);
            ulonglong2 q1 = *reinterpret_cast<const ulonglong2*>(&Bs[buf][kk][tx * 8 + 4]);
            unsigned long long ap;
            ap = packdup(a4.x);
            fma2(acc2[0][0], ap, q0.x); fma2(acc2[0][1], ap, q0.y);
            fma2(acc2[0][2], ap, q1.x); fma2(acc2[0][3], ap, q1.y);
            ap = packdup(a4.y);
            fma2(acc2[1][0], ap, q0.x); fma2(acc2[1][1], ap, q0.y);
            fma2(acc2[1][2], ap, q1.x); fma2(acc2[1][3], ap, q1.y);
            ap = packdup(a4.z);
            fma2(acc2[2][0], ap, q0.x); fma2(acc2[2][1], ap, q0.y);
            fma2(acc2[2][2], ap, q1.x); fma2(acc2[2][3], ap, q1.y);
            ap = packdup(a4.w);
            fma2(acc2[3][0], ap, q0.x); fma2(acc2[3][1], ap, q0.y);
            fma2(acc2[3][2], ap, q1.x); fma2(acc2[3][3], ap, q1.y);
        }
        // --- store prefetched tile into SMEM[buf^1] ---
        if (more) {
            const int nb = buf ^ 1;
            As[nb][ac + 0][ar] = pa.x; As[nb][ac + 1][ar] = pa.y;
            As[nb][ac + 2][ar] = pa.z; As[nb][ac + 3][ar] = pa.w;
            Bs[nb][bc + 0][br] = pb0.x; Bs[nb][bc + 1][br] = pb0.y;
            Bs[nb][bc + 2][br] = pb0.z; Bs[nb][bc + 3][br] = pb0.w;
            Bs[nb][bc + 4][br] = pb1.x; Bs[nb][bc + 5][br] = pb1.y;
            Bs[nb][bc + 6][br] = pb1.z; Bs[nb][bc + 7][br] = pb1.w;
            __syncthreads();
        }
    }

#pragma unroll
    for (int i = 0; i < 4; i++) {
        int row = bm + ty * 4 + i;                        // M % 64 == 0, always valid
        float* crow = C + (size_t)row * O;
#pragma unroll
        for (int g = 0; g < 2; g++) {
            int col = bn + tx * 8 + g * 4;
            if (col < O) {                                // O % 4 == 0 -> group all-or-none
                float x0, x1, x2, x3;
                unpack2(acc2[i][g * 2 + 0], x0, x1);
                unpack2(acc2[i][g * 2 + 1], x2, x3);
                float4 v = make_float4(x0 + bias[col], x1 + bias[col + 1],
                                       x2 + bias[col + 2], x3 + bias[col + 3]);
                if (relu) {
                    v.x = fmaxf(v.x, 0.f); v.y = fmaxf(v.y, 0.f);
                    v.z = fmaxf(v.z, 0.f); v.w = fmaxf(v.w, 0.f);
                }
                *reinterpret_cast<float4*>(crow + col) = v;
            }
        }
    }
}

// ---------------- GRU combine ----------------
__global__ void gru_kernel()
{
    int idx = blockIdx.x * blockDim.x + threadIdx.x;
    if (idx >= BE * MEMD) return;
    int b = idx / MEMD, j = idx - b * MEMD;
    const float* gi = g_GI + (size_t)b * GD;
    float ir = gi[j], iz = gi[172 + j], inn = gi[344 + j];
    {
        const float* gh = g_GH + (size_t)b * GD;
        float h = g_X[(size_t)b * XD + j];
        float r = sigm(ir + gh[j]);
        float z = sigm(iz + gh[172 + j]);
        float n = tanhf(inn + r * gh[344 + j]);
        g_newmem[(size_t)b * MEMD + j] = (1.f - z) * n + z * h;
    }
    {
        const float* gh = g_GH + (size_t)(BE + b) * GD;
        float h = g_X[(size_t)b * XD + 172 + j];
        float r = sigm(ir + gh[j]);
        float z = sigm(iz + gh[172 + j]);
        float n = tanhf(inn + r * gh[344 + j]);
        g_newmem[(size_t)(BE + b) * MEMD + j] = (1.f - z) * n + z * h;
    }
}

// ---------------- scatter priority (last-index-wins: dst over src, high idx wins) ----------------
__global__ void scatter_kernel(const int* __restrict__ src, const int* __restrict__ dst)
{
    int i = blockIdx.x * blockDim.x + threadIdx.x;
    if (i >= NB2) return;
    int node = (i < BE) ? src[i] : dst[i - BE];
    atomicMax(&g_upd[node], i + 1);
}

__global__ void clean_kernel(const int* __restrict__ src, const int* __restrict__ dst)
{
    int i = blockIdx.x * blockDim.x + threadIdx.x;
    if (i >= NB2) return;
    int node = (i < BE) ? src[i] : dst[i - BE];
    g_upd[node] = 0;
}

// ---------------- resolve gather indices once (pulls upd[] out of GEMM hot loop) ----------------
__global__ void resolve_nbr_kernel(const int* __restrict__ nid)
{
    int r = blockIdx.x * blockDim.x + threadIdx.x;
    if (r >= NBRROWS) return;
    int node = nid[r];
    int u = g_upd[node];
    g_nridx[r] = (u > 0) ? -u : node;     // negative -> g_newmem row (-v-1)
}

__global__ void resolve_node_kernel(const int* __restrict__ src, const int* __restrict__ dst)
{
    int i = blockIdx.x * blockDim.x + threadIdx.x;
    if (i >= NB2) return;
    int node = (i < BE) ? src[i] : dst[i - BE];
    int u = g_upd[node];
    g_nodeidx[i] = (u > 0) ? -u : node;
}

// ---------------- attention (2 heads x 10 neighbors) -> raw AO (o_W folded downstream) --------
__global__ void attn_kernel(const float* __restrict__ Q, const float* __restrict__ KV,
                            float* __restrict__ AO)
{
    int m = blockIdx.x;
    __shared__ float qs[EDD];
    __shared__ float att[2][KN];
    int t = threadIdx.x;
    if (t < EDD) qs[t] = Q[(size_t)m * EDD + t];
    __syncthreads();
    if (t < 2 * KN) {
        int h = t / KN, k = t - h * KN;
        const float* kr = KV + (size_t)(m * KN + k) * 200 + h * 50;
        const float* qh = qs + h * 50;
        float s = 0.f;
#pragma unroll 10
        for (int j = 0; j < 50; j++) s += qh[j] * kr[j];
        att[h][k] = s * 0.14142135623730951f;   // 1/sqrt(50)
    }
    __syncthreads();
    if (t < 2) {
        float mx = -1e30f;
        for (int k = 0; k < KN; k++) mx = fmaxf(mx, att[t][k]);
        float e[KN]; float sum = 0.f;
        for (int k = 0; k < KN; k++) { e[k] = expf(att[t][k] - mx); sum += e[k]; }
        float inv = 1.f / sum;
        for (int k = 0; k < KN; k++) att[t][k] = e[k] * inv;
    }
    __syncthreads();
    if (t < EDD) {
        int h = t / 50;
        float s = 0.f;
#pragma unroll
        for (int k = 0; k < KN; k++)
            s += att[h][k] * KV[(size_t)(m * KN + k) * 200 + 100 + t];
        AO[(size_t)m * EDD + t] = s;
    }
}

// ---------------- final score ----------------
__global__ void score_kernel(const float* __restrict__ H1F, const float* __restrict__ pW2,
                             const float* __restrict__ pb2, float* __restrict__ out)
{
    int warp = (blockIdx.x * blockDim.x + threadIdx.x) >> 5;
    int lane = threadIdx.x & 31;
    if (warp >= BE) return;
    const float* h = H1F + (size_t)warp * HIDD;
    float s = 0.f;
#pragma unroll
    for (int j = lane; j < HIDD; j += 32) s += h[j] * pW2[j];
#pragma unroll
    for (int o = 16; o > 0; o >>= 1) s += __shfl_xor_sync(0xffffffffu, s, o);
    if (lane == 0) out[warp] = 1.f / (1.f + expf(-(s + pb2[0])));
}

// ---------------- host-side ----------------
template <class L>
static void run_gemm(const L& ld, const float* W, const float* b, float* C,
                     int M, int I, int O, int relu)
{
    dim3 grid(M / BMT, (O + BNT - 1) / BNT);
    gemm_kernel<L><<<grid, 256>>>(ld, W, b, C, M, I, O, relu);
}

extern "C" void kernel_launch(void* const* d_in, const int* in_sizes, int n_in,
                              void* d_out, int out_size)
{
    (void)in_sizes; (void)n_in; (void)out_size;
    const float* memory  = (const float*)d_in[0];
    const int*   src     = (const int*)  d_in[1];
    const int*   dst     = (const int*)  d_in[2];
    const float* dt      = (const float*)d_in[3];
    const int*   nids    = (const int*)  d_in[4];
    const float* ndt     = (const float*)d_in[5];
    const float* t_w     = (const float*)d_in[6];
    const float* t_b     = (const float*)d_in[7];
    const float* m_W1    = (const float*)d_in[8];
    const float* m_b1    = (const float*)d_in[9];
    const float* m_W2    = (const float*)d_in[10];
    const float* m_b2    = (const float*)d_in[11];
    const float* g_Wih   = (const float*)d_in[12];
    const float* g_Whh   = (const float*)d_in[13];
    const float* g_bih   = (const float*)d_in[14];
    const float* g_bhh   = (const float*)d_in[15];
    const float* k_W     = (const float*)d_in[16];
    const float* k_b     = (const float*)d_in[17];
    const float* v_W     = (const float*)d_in[18];
    const float* v_b     = (const float*)d_in[19];
    const float* q_W     = (const float*)d_in[20];
    const float* q_b     = (const float*)d_in[21];
    const float* in_W    = (const float*)d_in[22];
    const float* in_b    = (const float*)d_in[23];
    const float* o_W     = (const float*)d_in[24];
    const float* o_b     = (const float*)d_in[25];
    const float* c_W     = (const float*)d_in[26];
    const float* c_b     = (const float*)d_in[27];
    const float* p_W1    = (const float*)d_in[28];
    const float* p_b1    = (const float*)d_in[29];
    const float* p_W2    = (const float*)d_in[30];
    const float* p_b2    = (const float*)d_in[31];
    float* out = (float*)d_out;

    float *dX, *dH1, *dRAW, *dGI, *dGH, *dNM, *dQ, *dKV, *dAO, *dZ, *dH1F;
    float *dCWkv, *dCWq, *dCWc, *dcb;
    int *dUPD, *dNRI, *dNI;
    cudaGetSymbolAddress((void**)&dX,    g_X);
    cudaGetSymbolAddress((void**)&dH1,   g_H1);
    cudaGetSymbolAddress((void**)&dRAW,  g_RAW);
    cudaGetSymbolAddress((void**)&dGI,   g_GI);
    cudaGetSymbolAddress((void**)&dGH,   g_GH);
    cudaGetSymbolAddress((void**)&dNM,   g_newmem);
    cudaGetSymbolAddress((void**)&dUPD,  g_upd);
    cudaGetSymbolAddress((void**)&dNRI,  g_nridx);
    cudaGetSymbolAddress((void**)&dNI,   g_nodeidx);
    cudaGetSymbolAddress((void**)&dQ,    g_Q);
    cudaGetSymbolAddress((void**)&dKV,   g_KV);
    cudaGetSymbolAddress((void**)&dAO,   g_AO);
    cudaGetSymbolAddress((void**)&dZ,    g_Z);
    cudaGetSymbolAddress((void**)&dH1F,  g_H1F);
    cudaGetSymbolAddress((void**)&dCWkv, g_CWkv);
    cudaGetSymbolAddress((void**)&dCWq,  g_CWq);
    cudaGetSymbolAddress((void**)&dCWc,  g_CWc);
    cudaGetSymbolAddress((void**)&dcb,   g_cb);

    // 1) fused weight precompute (single merged launch)
    prepw_kernel<<<(PREPW_TOTAL + 255) / 256, 256>>>(in_W, in_b, k_W, k_b, v_W, v_b,
                                                     q_W, q_b, c_W, c_b, o_W, o_b);

    // 2) X = [s_src | s_dst | time_enc(dt)]
    prepx_kernel<<<BE, 128>>>(memory, src, dst, dt, t_w, t_b);

    // 3) message MLP
    run_gemm(DenseLd{dX, XD, 0},    m_W1, m_b1, dH1,  BE, XD,   MSGD, 1);
    run_gemm(DenseLd{dH1, MSGD, 0}, m_W2, m_b2, dRAW, BE, MSGD, MSGD, 0);

    // 4) GRU gates: gi (shared) + gh (src/dst fused into one M=2B GEMM)
    run_gemm(DenseLd{dRAW, MSGD, 0}, g_Wih, g_bih, dGI, BE,  MSGD, GD, 0);
    run_gemm(GHLd{dX},               g_Whh, g_bhh, dGH, NB2, MEMD, GD, 0);
    gru_kernel<<<(BE * MEMD + 255) / 256, 256>>>();

    // 5) scatter winners + resolve gather indices once
    scatter_kernel<<<NB2 / 256, 256>>>(src, dst);
    resolve_nbr_kernel <<<NBRROWS / 256, 256>>>(nids);
    resolve_node_kernel<<<NB2 / 256, 256>>>(src, dst);

    // 6) attention projections on updated memory (fused in_W weights)
    NodeLd nodeld{memory, dNM, dNI};
    run_gemm(nodeld, dCWq, dcb + 200, dQ, NB2, MEMD, EDD, 0);
    run_gemm(NbrLd{memory, dNM, dNRI, ndt, t_w, t_b},
             dCWkv, dcb, dKV, NBRROWS, 272, 200, 0);

    // 7) softmax attention
    attn_kernel<<<NB2, 128>>>(dQ, dKV, dAO);

    // 8) z = relu([node_mem | ao_raw] @ CWc^T + cbc)   (o_W folded)
    run_gemm(NodeAOLd{nodeld, dAO}, dCWc, dcb + 300, dZ, NB2, 272, MSGD, 1);

    // 9) link predictor
    run_gemm(ZPairLd{dZ}, p_W1, p_b1, dH1F, BE, 200, HIDD, 1);
    score_kernel<<<(BE * 32 + 255) / 256, 256>>>(dH1F, p_W2, p_b2, out);

    // 10) restore upd[] for deterministic graph replay
    clean_kernel<<<NB2 / 256, 256>>>(src, dst);
}

// round 10
// speedup vs baseline: 1.5443x; 1.5066x over previous
#include <cuda_runtime.h>
#include <math.h>

// ---------------- problem constants ----------------
#define NNODES 1000000
#define MEMD   172
#define MSGD   100
#define EDD    100
#define KN     10
#define BE     32768      // batch of edges
#define NB2    65536      // 2*BE nodes
#define NBRROWS 655360    // 2*BE*KN
#define HIDD   128
#define XD     444        // 172+172+100
#define GD     516        // 3*172

// ---------------- device scratch (no cudaMalloc allowed) ----------------
__device__ float g_X[BE * XD];
__device__ float g_H1[BE * MSGD];
__device__ float g_RAW[BE * MSGD];
__device__ float g_GI[BE * GD];
__device__ float g_GH[NB2 * GD];          // rows [0,BE)=src side, [BE,2BE)=dst side
__device__ float g_newmem[NB2 * MEMD];
__device__ int   g_upd[NNODES];           // 0 = untouched, else winner_index+1
__device__ int   g_nridx[NBRROWS];        // resolved gather index for neighbor rows
__device__ int   g_nodeidx[NB2];          // resolved gather index for node rows
__device__ float g_Q[NB2 * EDD];
__device__ float g_KV[NBRROWS * 200];     // [kh(100) | vh(100)]
__device__ float g_AO[NB2 * EDD];
__device__ float g_Z[NB2 * MSGD];
__device__ float g_H1F[BE * HIDD];
__device__ float g_CWkv[200 * 272];       // fused (Wk@k_W ; Wv@v_W)
__device__ float g_CWq[100 * 172];        // fused Wq@q_W
__device__ float g_CWc[100 * 272];        // c_W with o_W folded into last 100 cols
__device__ float g_cb[400];               // [0,200) kv bias, [200,300) q bias, [300,400) c bias

// ---------------- helpers ----------------
__device__ __forceinline__ float sigm(float x) { return 1.f / (1.f + expf(-x)); }

__device__ __forceinline__ unsigned long long packdup(float x) {
    unsigned long long v;
    asm("mov.b64 %0, {%1, %1};" : "=l"(v) : "r"(__float_as_uint(x)));
    return v;
}
__device__ __forceinline__ void fma2(unsigned long long& d, unsigned long long a,
                                     unsigned long long b) {
    asm("fma.rn.f32x2 %0, %1, %2, %0;" : "+l"(d) : "l"(a), "l"(b));
}
__device__ __forceinline__ void unpack2(unsigned long long v, float& lo, float& hi) {
    unsigned int a, b;
    asm("mov.b64 {%0, %1}, %2;" : "=r"(a), "=r"(b) : "l"(v));
    lo = __uint_as_float(a); hi = __uint_as_float(b);
}

// ---------------- merged weight-prep kernel ----------------
// work ranges: [0, 54400)        cw_kv  (200 x 272)
//              [54400, 71600)    cw_q   (100 x 172)
//              [71600, 98800)    cw_c   (100 x 272)
//              [98800, 99200)    cb     (400)
#define PREPW_TOTAL 99200
__global__ void prepw_kernel(const float* __restrict__ inW, const float* __restrict__ inB,
                             const float* __restrict__ kW,  const float* __restrict__ kb,
                             const float* __restrict__ vW,  const float* __restrict__ vb,
                             const float* __restrict__ qW,  const float* __restrict__ qb,
                             const float* __restrict__ cW,  const float* __restrict__ cb_,
                             const float* __restrict__ oW,  const float* __restrict__ ob)
{
    int idx = blockIdx.x * blockDim.x + threadIdx.x;
    if (idx < 54400) {
        int o = idx / 272, i = idx - o * 272;
        const float* Wrow = inW + (100 + o) * 100;      // o<100 -> Wk rows, o>=100 -> Wv rows
        const float* Msel = (o < 100) ? kW : vW;
        float s = 0.f;
        for (int j = 0; j < 100; j++) s += Wrow[j] * Msel[j * 272 + i];
        g_CWkv[idx] = s;
    } else if (idx < 71600) {
        int q = idx - 54400;
        int o = q / 172, i = q - o * 172;
        const float* Wrow = inW + o * 100;              // Wq rows [0,100)
        float s = 0.f;
        for (int j = 0; j < 100; j++) s += Wrow[j] * qW[j * 172 + i];
        g_CWq[q] = s;
    } else if (idx < 98800) {
        int q = idx - 71600;
        int o = q / 272, i = q - o * 272;
        if (i < 172) {
            g_CWc[q] = cW[o * 272 + i];
        } else {
            int c2 = i - 172;
            float s = 0.f;
            for (int d = 0; d < 100; d++) s += cW[o * 272 + 172 + d] * oW[d * 100 + c2];
            g_CWc[q] = s;
        }
    } else if (idx < PREPW_TOTAL) {
        int t = idx - 98800;
        if (t < 200) {
            int o = t;
            const float* Wrow = inW + (100 + o) * 100;
            const float* bsel = (o < 100) ? kb : vb;
            float s = inB[100 + o];
            for (int j = 0; j < 100; j++) s += Wrow[j] * bsel[j];
            g_cb[t] = s;
        } else if (t < 300) {
            int o = t - 200;
            const float* Wrow = inW + o * 100;
            float s = inB[o];
            for (int j = 0; j < 100; j++) s += Wrow[j] * qb[j];
            g_cb[t] = s;
        } else {
            int o = t - 300;
            float s = cb_[o];
            for (int d = 0; d < 100; d++) s += cW[o * 272 + 172 + d] * ob[d];
            g_cb[t] = s;
        }
    }
}

// ---------------- prep: X = [mem[src] | mem[dst] | sin(dt*tw+tb)] ----------------
__global__ void prepx_kernel(const float* __restrict__ mem,
                             const int* __restrict__ src, const int* __restrict__ dst,
                             const float* __restrict__ dt,
                             const float* __restrict__ tw, const float* __restrict__ tb)
{
    int b = blockIdx.x, t = threadIdx.x;           // 128 threads
    float4* xr = reinterpret_cast<float4*>(g_X + (size_t)b * XD);
    for (int q = t; q < 111; q += 128) {           // 43 + 43 + 25 float4 chunks
        float4 v;
        if (q < 43) {
            v = *reinterpret_cast<const float4*>(mem + (size_t)src[b] * MEMD + q * 4);
        } else if (q < 86) {
            v = *reinterpret_cast<const float4*>(mem + (size_t)dst[b] * MEMD + (q - 43) * 4);
        } else {
            int j = (q - 86) * 4;
            float d = dt[b];
            v = make_float4(__sinf(d * tw[j]     + tb[j]),
                            __sinf(d * tw[j + 1] + tb[j + 1]),
                            __sinf(d * tw[j + 2] + tb[j + 2]),
                            __sinf(d * tw[j + 3] + tb[j + 3]));
        }
        xr[q] = v;
    }
}

// ---------------- A-operand loaders: init(r) caches the resolved row once ----------------
struct DenseLd {
    const float* A; int lda; int off;
    const float* p;
    __device__ __forceinline__ void init(int r) { p = A + (size_t)r * lda + off; }
    __device__ __forceinline__ float4 ld4(int c) const {
        return *reinterpret_cast<const float4*>(p + c);
    }
};
struct GHLd {   // rows [0,BE): X cols [0,172); rows [BE,2BE): X cols [172,344)
    const float* X;
    const float* p;
    __device__ __forceinline__ void init(int r) {
        int rr  = (r < BE) ? r : r - BE;
        int off = (r < BE) ? 0 : 172;
        p = X + (size_t)rr * XD + off;
    }
    __device__ __forceinline__ float4 ld4(int c) const {
        return *reinterpret_cast<const float4*>(p + c);
    }
};
struct NodeLd {
    const float* mem; const float* nmem; const int* idx;
    const float* p;
    __device__ __forceinline__ void init(int r) {
        int i = idx[r];
        p = (i >= 0) ? mem + (size_t)i * MEMD : nmem + (size_t)(-i - 1) * MEMD;
    }
    __device__ __forceinline__ float4 ld4(int c) const {
        return *reinterpret_cast<const float4*>(p + c);
    }
};
struct NbrLd {
    const float* mem; const float* nmem; const int* idx;
    const float* ndt; const float* tw; const float* tb;
    const float* p; float d;
    __device__ __forceinline__ void init(int r) {
        int i = idx[r];
        p = (i >= 0) ? mem + (size_t)i * MEMD : nmem + (size_t)(-i - 1) * MEMD;
        d = ndt[r];
    }
    __device__ __forceinline__ float4 ld4(int c) const {
        if (c < MEMD) return *reinterpret_cast<const float4*>(p + c);
        int j = c - MEMD;
        return make_float4(__sinf(d * tw[j]     + tb[j]),
                           __sinf(d * tw[j + 1] + tb[j + 1]),
                           __sinf(d * tw[j + 2] + tb[j + 2]),
                           __sinf(d * tw[j + 3] + tb[j + 3]));
    }
};
struct NodeAOLd {
    NodeLd nl; const float* ao;
    const float* pao;
    __device__ __forceinline__ void init(int r) {
        nl.init(r);
        pao = ao + (size_t)r * EDD;
    }
    __device__ __forceinline__ float4 ld4(int c) const {
        if (c < MEMD) return nl.ld4(c);
        return *reinterpret_cast<const float4*>(pao + (c - MEMD));
    }
};
struct ZPairLd {
    const float* Z;
    const float* p0; const float* p1;
    __device__ __forceinline__ void init(int r) {
        p0 = Z + (size_t)r * 100;
        p1 = Z + (size_t)(r + BE) * 100;
    }
    __device__ __forceinline__ float4 ld4(int c) const {
        if (c < 100) return *reinterpret_cast<const float4*>(p0 + c);
        return *reinterpret_cast<const float4*>(p1 + (c - 100));
    }
};

// ---------------- generic fused-gather SGEMM, double-buffered, conflict-free LDS ----------
// C[M,O] = act(A[M,I] @ W[O,I]^T + bias); M % 64 == 0, I % 4 == 0, O % 4 == 0.
// 64x128 tile, BK=16, 256 threads, 4x8 per-thread register tile, packed f32x2 FMA.
// Per-thread columns: {tx*4..tx*4+3} and {64+tx*4..64+tx*4+3}  (16B-contiguous across
// the 16 tx lanes -> zero-bank-conflict LDS.128; the old tx*8 mapping had 128B-aliased
// addresses -> 4-way conflicts and made L1tex the binding pipe at 72%).
constexpr int BMT = 64, BNT = 128, BKT = 16;

template <class L>
__global__ __launch_bounds__(256, 3)
void gemm_kernel(L ld, const float* __restrict__ W, const float* __restrict__ bias,
                 float* __restrict__ C, int M, int I, int O, int relu)
{
    __shared__ __align__(16) float As[2][BKT][BMT + 4];   // 68 floats/row (272B, 16B mult)
    __shared__ __align__(16) float Bs[2][BKT][BNT + 4];   // 132 floats/row (528B, 16B mult)
    const int t  = threadIdx.x;
    const int tx = t & 15, ty = t >> 4;                   // 16 x 16 thread grid
    const int bm = blockIdx.x * BMT, bn = blockIdx.y * BNT;
    // A load map: 256 threads x one float4 = 64 rows x 16 cols
    const int ar = t >> 2, ac = (t & 3) * 4;
    // B load map: 256 threads x two float4 = 128 rows x 16 cols
    const int br = t >> 1, bc = (t & 1) * 8;
    const bool bvalid = (bn + br) < O;
    const float* wrow = W + (size_t)(bn + br) * I + bc;

    ld.init(bm + ar);                                     // resolve gather row ONCE

    unsigned long long acc2[4][4];   // [row i][g*2+pair]: g=0 -> cols tx*4, g=1 -> cols 64+tx*4
#pragma unroll
    for (int i = 0; i < 4; i++)
#pragma unroll
        for (int j = 0; j < 4; j++) acc2[i][j] = 0ULL;

    const int steps = (I + BKT - 1) / BKT;

    float4 pa, pb0, pb1;
    // --- prologue: fetch tile 0 ---
    {
        pa = make_float4(0.f, 0.f, 0.f, 0.f);
        if (ac < I) pa = ld.ld4(ac);
        pb0 = make_float4(0.f, 0.f, 0.f, 0.f); pb1 = pb0;
        if (bvalid) {
            if (bc + 3 < I) pb0 = *reinterpret_cast<const float4*>(wrow);
            if (bc + 7 < I) pb1 = *reinterpret_cast<const float4*>(wrow + 4);
        }
        As[0][ac + 0][ar] = pa.x; As[0][ac + 1][ar] = pa.y;
        As[0][ac + 2][ar] = pa.z; As[0][ac + 3][ar] = pa.w;
        Bs[0][bc + 0][br] = pb0.x; Bs[0][bc + 1][br] = pb0.y;
        Bs[0][bc + 2][br] = pb0.z; Bs[0][bc + 3][br] = pb0.w;
        Bs[0][bc + 4][br] = pb1.x; Bs[0][bc + 5][br] = pb1.y;
        Bs[0][bc + 6][br] = pb1.z; Bs[0][bc + 7][br] = pb1.w;
    }
    __syncthreads();

    for (int s = 0; s < steps; s++) {
        const int buf = s & 1;
        const bool more = (s + 1) < steps;
        // --- prefetch tile s+1 into registers ---
        if (more) {
            const int k0 = (s + 1) * BKT;
            pa = make_float4(0.f, 0.f, 0.f, 0.f);
            if (k0 + ac < I) pa = ld.ld4(k0 + ac);
            pb0 = make_float4(0.f, 0.f, 0.f, 0.f); pb1 = pb0;
            if (bvalid) {
                if (k0 + bc + 3 < I) pb0 = *reinterpret_cast<const float4*>(wrow + k0);
                if (k0 + bc + 7 < I) pb1 = *reinterpret_cast<const float4*>(wrow + k0 + 4);
            }
        }
        // --- compute tile s from SMEM[buf] (conflict-free fragment loads) ---
#pragma unroll
        for (int kk = 0; kk < BKT; kk++) {
            float4 a4 = *reinterpret_cast<const float4*>(&As[buf][kk][ty * 4]);
            ulonglong2 q0 = *reinterpret_cast<const ulonglong2*>(&Bs[buf][kk][tx * 4]);
            ulonglong2 q1 = *reinterpret_cast<const ulonglong2*>(&Bs[buf][kk][64 + tx * 4]);
            unsigned long long ap;
            ap = packdup(a4.x);
            fma2(acc2[0][0], ap, q0.x); fma2(acc2[0][1], ap, q0.y);
            fma2(acc2[0][2], ap, q1.x); fma2(acc2[0][3], ap, q1.y);
            ap = packdup(a4.y);
            fma2(acc2[1][0], ap, q0.x); fma2(acc2[1][1], ap, q0.y);
            fma2(acc2[1][2], ap, q1.x); fma2(acc2[1][3], ap, q1.y);
            ap = packdup(a4.z);
            fma2(acc2[2][0], ap, q0.x); fma2(acc2[2][1], ap, q0.y);
            fma2(acc2[2][2], ap, q1.x); fma2(acc2[2][3], ap, q1.y);
            ap = packdup(a4.w);
            fma2(acc2[3][0], ap, q0.x); fma2(acc2[3][1], ap, q0.y);
            fma2(acc2[3][2], ap, q1.x); fma2(acc2[3][3], ap, q1.y);
        }
        // --- store prefetched tile into SMEM[buf^1] ---
        if (more) {
            const int nb = buf ^ 1;
            As[nb][ac + 0][ar] = pa.x; As[nb][ac + 1][ar] = pa.y;
            As[nb][ac + 2][ar] = pa.z; As[nb][ac + 3][ar] = pa.w;
            Bs[nb][bc + 0][br] = pb0.x; Bs[nb][bc + 1][br] = pb0.y;
            Bs[nb][bc + 2][br] = pb0.z; Bs[nb][bc + 3][br] = pb0.w;
            Bs[nb][bc + 4][br] = pb1.x; Bs[nb][bc + 5][br] = pb1.y;
            Bs[nb][bc + 6][br] = pb1.z; Bs[nb][bc + 7][br] = pb1.w;
            __syncthreads();
        }
    }

#pragma unroll
    for (int i = 0; i < 4; i++) {
        int row = bm + ty * 4 + i;                        // M % 64 == 0, always valid
        float* crow = C + (size_t)row * O;
#pragma unroll
        for (int g = 0; g < 2; g++) {
            int col = bn + g * 64 + tx * 4;
            if (col < O) {                                // O % 4 == 0 -> group all-or-none
                float x0, x1, x2, x3;
                unpack2(acc2[i][g * 2 + 0], x0, x1);
                unpack2(acc2[i][g * 2 + 1], x2, x3);
                float4 v = make_float4(x0 + bias[col], x1 + bias[col + 1],
                                       x2 + bias[col + 2], x3 + bias[col + 3]);
                if (relu) {
                    v.x = fmaxf(v.x, 0.f); v.y = fmaxf(v.y, 0.f);
                    v.z = fmaxf(v.z, 0.f); v.w = fmaxf(v.w, 0.f);
                }
                *reinterpret_cast<float4*>(crow + col) = v;
            }
        }
    }
}

// ---------------- GRU combine ----------------
__global__ void gru_kernel()
{
    int idx = blockIdx.x * blockDim.x + threadIdx.x;
    if (idx >= BE * MEMD) return;
    int b = idx / MEMD, j = idx - b * MEMD;
    const float* gi = g_GI + (size_t)b * GD;
    float ir = gi[j], iz = gi[172 + j], inn = gi[344 + j];
    {
        const float* gh = g_GH + (size_t)b * GD;
        float h = g_X[(size_t)b * XD + j];
        float r = sigm(ir + gh[j]);
        float z = sigm(iz + gh[172 + j]);
        float n = tanhf(inn + r * gh[344 + j]);
        g_newmem[(size_t)b * MEMD + j] = (1.f - z) * n + z * h;
    }
    {
        const float* gh = g_GH + (size_t)(BE + b) * GD;
        float h = g_X[(size_t)b * XD + 172 + j];
        float r = sigm(ir + gh[j]);
        float z = sigm(iz + gh[172 + j]);
        float n = tanhf(inn + r * gh[344 + j]);
        g_newmem[(size_t)(BE + b) * MEMD + j] = (1.f - z) * n + z * h;
    }
}

// ---------------- scatter priority (last-index-wins: dst over src, high idx wins) ----------------
__global__ void scatter_kernel(const int* __restrict__ src, const int* __restrict__ dst)
{
    int i = blockIdx.x * blockDim.x + threadIdx.x;
    if (i >= NB2) return;
    int node = (i < BE) ? src[i] : dst[i - BE];
    atomicMax(&g_upd[node], i + 1);
}

__global__ void clean_kernel(const int* __restrict__ src, const int* __restrict__ dst)
{
    int i = blockIdx.x * blockDim.x + threadIdx.x;
    if (i >= NB2) return;
    int node = (i < BE) ? src[i] : dst[i - BE];
    g_upd[node] = 0;
}

// ---------------- resolve gather indices once ----------------
__global__ void resolve_nbr_kernel(const int* __restrict__ nid)
{
    int r = blockIdx.x * blockDim.x + threadIdx.x;
    if (r >= NBRROWS) return;
    int node = nid[r];
    int u = g_upd[node];
    g_nridx[r] = (u > 0) ? -u : node;     // negative -> g_newmem row (-v-1)
}

__global__ void resolve_node_kernel(const int* __restrict__ src, const int* __restrict__ dst)
{
    int i = blockIdx.x * blockDim.x + threadIdx.x;
    if (i >= NB2) return;
    int node = (i < BE) ? src[i] : dst[i - BE];
    int u = g_upd[node];
    g_nodeidx[i] = (u > 0) ? -u : node;
}

// ---------------- attention (2 heads x 10 neighbors) -> raw AO ----------------
__global__ void attn_kernel(const float* __restrict__ Q, const float* __restrict__ KV,
                            float* __restrict__ AO)
{
    int m = blockIdx.x;
    __shared__ float qs[EDD];
    __shared__ float att[2][KN];
    int t = threadIdx.x;
    if (t < EDD) qs[t] = Q[(size_t)m * EDD + t];
    __syncthreads();
    if (t < 2 * KN) {
        int h = t / KN, k = t - h * KN;
        const float* kr = KV + (size_t)(m * KN + k) * 200 + h * 50;
        const float* qh = qs + h * 50;
        float s = 0.f;
#pragma unroll 10
        for (int j = 0; j < 50; j++) s += qh[j] * kr[j];
        att[h][k] = s * 0.14142135623730951f;   // 1/sqrt(50)
    }
    __syncthreads();
    if (t < 2) {
        float mx = -1e30f;
        for (int k = 0; k < KN; k++) mx = fmaxf(mx, att[t][k]);
        float e[KN]; float sum = 0.f;
        for (int k = 0; k < KN; k++) { e[k] = expf(att[t][k] - mx); sum += e[k]; }
        float inv = 1.f / sum;
        for (int k = 0; k < KN; k++) att[t][k] = e[k] * inv;
    }
    __syncthreads();
    if (t < EDD) {
        int h = t / 50;
        float s = 0.f;
#pragma unroll
        for (int k = 0; k < KN; k++)
            s += att[h][k] * KV[(size_t)(m * KN + k) * 200 + 100 + t];
        AO[(size_t)m * EDD + t] = s;
    }
}

// ---------------- final score ----------------
__global__ void score_kernel(const float* __restrict__ H1F, const float* __restrict__ pW2,
                             const float* __restrict__ pb2, float* __restrict__ out)
{
    int warp = (blockIdx.x * blockDim.x + threadIdx.x) >> 5;
    int lane = threadIdx.x & 31;
    if (warp >= BE) return;
    const float* h = H1F + (size_t)warp * HIDD;
    float s = 0.f;
#pragma unroll
    for (int j = lane; j < HIDD; j += 32) s += h[j] * pW2[j];
#pragma unroll
    for (int o = 16; o > 0; o >>= 1) s += __shfl_xor_sync(0xffffffffu, s, o);
    if (lane == 0) out[warp] = 1.f / (1.f + expf(-(s + pb2[0])));
}

// ---------------- host-side ----------------
template <class L>
static void run_gemm(const L& ld, const float* W, const float* b, float* C,
                     int M, int I, int O, int relu)
{
    dim3 grid(M / BMT, (O + BNT - 1) / BNT);
    gemm_kernel<L><<<grid, 256>>>(ld, W, b, C, M, I, O, relu);
}

extern "C" void kernel_launch(void* const* d_in, const int* in_sizes, int n_in,
                              void* d_out, int out_size)
{
    (void)in_sizes; (void)n_in; (void)out_size;
    const float* memory  = (const float*)d_in[0];
    const int*   src     = (const int*)  d_in[1];
    const int*   dst     = (const int*)  d_in[2];
    const float* dt      = (const float*)d_in[3];
    const int*   nids    = (const int*)  d_in[4];
    const float* ndt     = (const float*)d_in[5];
    const float* t_w     = (const float*)d_in[6];
    const float* t_b     = (const float*)d_in[7];
    const float* m_W1    = (const float*)d_in[8];
    const float* m_b1    = (const float*)d_in[9];
    const float* m_W2    = (const float*)d_in[10];
    const float* m_b2    = (const float*)d_in[11];
    const float* g_Wih   = (const float*)d_in[12];
    const float* g_Whh   = (const float*)d_in[13];
    const float* g_bih   = (const float*)d_in[14];
    const float* g_bhh   = (const float*)d_in[15];
    const float* k_W     = (const float*)d_in[16];
    const float* k_b     = (const float*)d_in[17];
    const float* v_W     = (const float*)d_in[18];
    const float* v_b     = (const float*)d_in[19];
    const float* q_W     = (const float*)d_in[20];
    const float* q_b     = (const float*)d_in[21];
    const float* in_W    = (const float*)d_in[22];
    const float* in_b    = (const float*)d_in[23];
    const float* o_W     = (const float*)d_in[24];
    const float* o_b     = (const float*)d_in[25];
    const float* c_W     = (const float*)d_in[26];
    const float* c_b     = (const float*)d_in[27];
    const float* p_W1    = (const float*)d_in[28];
    const float* p_b1    = (const float*)d_in[29];
    const float* p_W2    = (const float*)d_in[30];
    const float* p_b2    = (const float*)d_in[31];
    float* out = (float*)d_out;

    float *dX, *dH1, *dRAW, *dGI, *dGH, *dNM, *dQ, *dKV, *dAO, *dZ, *dH1F;
    float *dCWkv, *dCWq, *dCWc, *dcb;
    int *dUPD, *dNRI, *dNI;
    cudaGetSymbolAddress((void**)&dX,    g_X);
    cudaGetSymbolAddress((void**)&dH1,   g_H1);
    cudaGetSymbolAddress((void**)&dRAW,  g_RAW);
    cudaGetSymbolAddress((void**)&dGI,   g_GI);
    cudaGetSymbolAddress((void**)&dGH,   g_GH);
    cudaGetSymbolAddress((void**)&dNM,   g_newmem);
    cudaGetSymbolAddress((void**)&dUPD,  g_upd);
    cudaGetSymbolAddress((void**)&dNRI,  g_nridx);
    cudaGetSymbolAddress((void**)&dNI,   g_nodeidx);
    cudaGetSymbolAddress((void**)&dQ,    g_Q);
    cudaGetSymbolAddress((void**)&dKV,   g_KV);
    cudaGetSymbolAddress((void**)&dAO,   g_AO);
    cudaGetSymbolAddress((void**)&dZ,    g_Z);
    cudaGetSymbolAddress((void**)&dH1F,  g_H1F);
    cudaGetSymbolAddress((void**)&dCWkv, g_CWkv);
    cudaGetSymbolAddress((void**)&dCWq,  g_CWq);
    cudaGetSymbolAddress((void**)&dCWc,  g_CWc);
    cudaGetSymbolAddress((void**)&dcb,   g_cb);

    // 1) fused weight precompute (single merged launch)
    prepw_kernel<<<(PREPW_TOTAL + 255) / 256, 256>>>(in_W, in_b, k_W, k_b, v_W, v_b,
                                                     q_W, q_b, c_W, c_b, o_W, o_b);

    // 2) X = [s_src | s_dst | time_enc(dt)]
    prepx_kernel<<<BE, 128>>>(memory, src, dst, dt, t_w, t_b);

    // 3) message MLP
    run_gemm(DenseLd{dX, XD, 0},    m_W1, m_b1, dH1,  BE, XD,   MSGD, 1);
    run_gemm(DenseLd{dH1, MSGD, 0}, m_W2, m_b2, dRAW, BE, MSGD, MSGD, 0);

    // 4) GRU gates: gi (shared) + gh (src/dst fused into one M=2B GEMM)
    run_gemm(DenseLd{dRAW, MSGD, 0}, g_Wih, g_bih, dGI, BE,  MSGD, GD, 0);
    run_gemm(GHLd{dX},               g_Whh, g_bhh, dGH, NB2, MEMD, GD, 0);
    gru_kernel<<<(BE * MEMD + 255) / 256, 256>>>();

    // 5) scatter winners + resolve gather indices once
    scatter_kernel<<<NB2 / 256, 256>>>(src, dst);
    resolve_nbr_kernel <<<NBRROWS / 256, 256>>>(nids);
    resolve_node_kernel<<<NB2 / 256, 256>>>(src, dst);

    // 6) attention projections on updated memory (fused in_W weights)
    NodeLd nodeld{memory, dNM, dNI};
    run_gemm(nodeld, dCWq, dcb + 200, dQ, NB2, MEMD, EDD, 0);
    run_gemm(NbrLd{memory, dNM, dNRI, ndt, t_w, t_b},
             dCWkv, dcb, dKV, NBRROWS, 272, 200, 0);

    // 7) softmax attention
    attn_kernel<<<NB2, 128>>>(dQ, dKV, dAO);

    // 8) z = relu([node_mem | ao_raw] @ CWc^T + cbc)   (o_W folded)
    run_gemm(NodeAOLd{nodeld, dAO}, dCWc, dcb + 300, dZ, NB2, 272, MSGD, 1);

    // 9) link predictor
    run_gemm(ZPairLd{dZ}, p_W1, p_b1, dH1F, BE, 200, HIDD, 1);
    score_kernel<<<(BE * 32 + 255) / 256, 256>>>(dH1F, p_W2, p_b2, out);

    // 10) restore upd[] for deterministic graph replay
    clean_kernel<<<NB2 / 256, 256>>>(src, dst);
}

// round 14
// speedup vs baseline: 1.7777x; 1.1511x over previous
#include <cuda_runtime.h>
#include <math.h>

// ---------------- problem constants ----------------
#define NNODES 1000000
#define MEMD   172
#define MSGD   100
#define EDD    100
#define KN     10
#define BE     32768      // batch of edges
#define NB2    65536      // 2*BE nodes
#define NBRROWS 655360    // 2*BE*KN
#define HIDD   128
#define XD     444        // 172+172+100
#define GD     516        // 3*172

// ---------------- device scratch (no cudaMalloc allowed) ----------------
__device__ float g_X[BE * XD];
__device__ float g_H1[BE * MSGD];
__device__ float g_RAW[BE * MSGD];
__device__ float g_GI[BE * GD];
__device__ float g_GH[NB2 * GD];          // rows [0,BE)=src side, [BE,2BE)=dst side
__device__ float g_newmem[NB2 * MEMD];
__device__ int   g_upd[NNODES];           // 0 = untouched, else winner_index+1
__device__ int   g_nridx[NBRROWS];        // resolved gather index for neighbor rows
__device__ int   g_nodeidx[NB2];          // resolved gather index for node rows
__device__ float g_Q[NB2 * EDD];
__device__ float g_KV[NBRROWS * 200];     // [kh(100) | vh(100)]
__device__ float g_AO[NB2 * EDD];
__device__ float g_Z[NB2 * MSGD];
__device__ float g_H1F[BE * HIDD];
__device__ float g_CWkv[200 * 272];       // fused (Wk@k_W ; Wv@v_W)
__device__ float g_CWq[100 * 172];        // fused Wq@q_W
__device__ float g_CWc[100 * 272];        // c_W with o_W folded into last 100 cols
__device__ float g_cb[400];               // [0,200) kv bias, [200,300) q bias, [300,400) c bias

// ---------------- helpers ----------------
__device__ __forceinline__ float sigm(float x) { return 1.f / (1.f + expf(-x)); }

__device__ __forceinline__ unsigned long long packdup(float x) {
    unsigned long long v;
    asm("mov.b64 %0, {%1, %1};" : "=l"(v) : "r"(__float_as_uint(x)));
    return v;
}
__device__ __forceinline__ void fma2(unsigned long long& d, unsigned long long a,
                                     unsigned long long b) {
    asm("fma.rn.f32x2 %0, %1, %2, %0;" : "+l"(d) : "l"(a), "l"(b));
}
__device__ __forceinline__ void unpack2(unsigned long long v, float& lo, float& hi) {
    unsigned int a, b;
    asm("mov.b64 {%0, %1}, %2;" : "=r"(a), "=r"(b) : "l"(v));
    lo = __uint_as_float(a); hi = __uint_as_float(b);
}

// ---------------- merged weight-prep kernel ----------------
// work ranges: [0, 54400)        cw_kv  (200 x 272)
//              [54400, 71600)    cw_q   (100 x 172)
//              [71600, 98800)    cw_c   (100 x 272)
//              [98800, 99200)    cb     (400)
#define PREPW_TOTAL 99200
__global__ void prepw_kernel(const float* __restrict__ inW, const float* __restrict__ inB,
                             const float* __restrict__ kW,  const float* __restrict__ kb,
                             const float* __restrict__ vW,  const float* __restrict__ vb,
                             const float* __restrict__ qW,  const float* __restrict__ qb,
                             const float* __restrict__ cW,  const float* __restrict__ cb_,
                             const float* __restrict__ oW,  const float* __restrict__ ob)
{
    int idx = blockIdx.x * blockDim.x + threadIdx.x;
    if (idx < 54400) {
        int o = idx / 272, i = idx - o * 272;
        const float* Wrow = inW + (100 + o) * 100;      // o<100 -> Wk rows, o>=100 -> Wv rows
        const float* Msel = (o < 100) ? kW : vW;
        float s = 0.f;
        for (int j = 0; j < 100; j++) s += Wrow[j] * Msel[j * 272 + i];
        g_CWkv[idx] = s;
    } else if (idx < 71600) {
        int q = idx - 54400;
        int o = q / 172, i = q - o * 172;
        const float* Wrow = inW + o * 100;              // Wq rows [0,100)
        float s = 0.f;
        for (int j = 0; j < 100; j++) s += Wrow[j] * qW[j * 172 + i];
        g_CWq[q] = s;
    } else if (idx < 98800) {
        int q = idx - 71600;
        int o = q / 272, i = q - o * 272;
        if (i < 172) {
            g_CWc[q] = cW[o * 272 + i];
        } else {
            int c2 = i - 172;
            float s = 0.f;
            for (int d = 0; d < 100; d++) s += cW[o * 272 + 172 + d] * oW[d * 100 + c2];
            g_CWc[q] = s;
        }
    } else if (idx < PREPW_TOTAL) {
        int t = idx - 98800;
        if (t < 200) {
            int o = t;
            const float* Wrow = inW + (100 + o) * 100;
            const float* bsel = (o < 100) ? kb : vb;
            float s = inB[100 + o];
            for (int j = 0; j < 100; j++) s += Wrow[j] * bsel[j];
            g_cb[t] = s;
        } else if (t < 300) {
            int o = t - 200;
            const float* Wrow = inW + o * 100;
            float s = inB[o];
            for (int j = 0; j < 100; j++) s += Wrow[j] * qb[j];
            g_cb[t] = s;
        } else {
            int o = t - 300;
            float s = cb_[o];
            for (int d = 0; d < 100; d++) s += cW[o * 272 + 172 + d] * ob[d];
            g_cb[t] = s;
        }
    }
}

// ---------------- prep: X = [mem[src] | mem[dst] | sin(dt*tw+tb)] ----------------
__global__ void prepx_kernel(const float* __restrict__ mem,
                             const int* __restrict__ src, const int* __restrict__ dst,
                             const float* __restrict__ dt,
                             const float* __restrict__ tw, const float* __restrict__ tb)
{
    int b = blockIdx.x, t = threadIdx.x;           // 128 threads
    float4* xr = reinterpret_cast<float4*>(g_X + (size_t)b * XD);
    for (int q = t; q < 111; q += 128) {           // 43 + 43 + 25 float4 chunks
        float4 v;
        if (q < 43) {
            v = *reinterpret_cast<const float4*>(mem + (size_t)src[b] * MEMD + q * 4);
        } else if (q < 86) {
            v = *reinterpret_cast<const float4*>(mem + (size_t)dst[b] * MEMD + (q - 43) * 4);
        } else {
            int j = (q - 86) * 4;
            float d = dt[b];
            v = make_float4(__sinf(d * tw[j]     + tb[j]),
                            __sinf(d * tw[j + 1] + tb[j + 1]),
                            __sinf(d * tw[j + 2] + tb[j + 2]),
                            __sinf(d * tw[j + 3] + tb[j + 3]));
        }
        xr[q] = v;
    }
}

// ---------------- A-operand loaders: init(r) caches the resolved row once ----------------
struct DenseLd {
    const float* A; int lda; int off;
    const float* p;
    __device__ __forceinline__ void init(int r) { p = A + (size_t)r * lda + off; }
    __device__ __forceinline__ float4 ld4(int c) const {
        return *reinterpret_cast<const float4*>(p + c);
    }
};
struct GHLd {   // rows [0,BE): X cols [0,172); rows [BE,2BE): X cols [172,344)
    const float* X;
    const float* p;
    __device__ __forceinline__ void init(int r) {
        int rr  = (r < BE) ? r : r - BE;
        int off = (r < BE) ? 0 : 172;
        p = X + (size_t)rr * XD + off;
    }
    __device__ __forceinline__ float4 ld4(int c) const {
        return *reinterpret_cast<const float4*>(p + c);
    }
};
struct NodeLd {
    const float* mem; const float* nmem; const int* idx;
    const float* p;
    __device__ __forceinline__ void init(int r) {
        int i = idx[r];
        p = (i >= 0) ? mem + (size_t)i * MEMD : nmem + (size_t)(-i - 1) * MEMD;
    }
    __device__ __forceinline__ float4 ld4(int c) const {
        return *reinterpret_cast<const float4*>(p + c);
    }
};
struct NbrLd {
    const float* mem; const float* nmem; const int* idx;
    const float* ndt; const float* tw; const float* tb;
    const float* p; float d;
    __device__ __forceinline__ void init(int r) {
        int i = idx[r];
        p = (i >= 0) ? mem + (size_t)i * MEMD : nmem + (size_t)(-i - 1) * MEMD;
        d = ndt[r];
    }
    __device__ __forceinline__ float4 ld4(int c) const {
        if (c < MEMD) return *reinterpret_cast<const float4*>(p + c);
        int j = c - MEMD;
        return make_float4(__sinf(d * tw[j]     + tb[j]),
                           __sinf(d * tw[j + 1] + tb[j + 1]),
                           __sinf(d * tw[j + 2] + tb[j + 2]),
                           __sinf(d * tw[j + 3] + tb[j + 3]));
    }
};
struct NodeAOLd {
    NodeLd nl; const float* ao;
    const float* pao;
    __device__ __forceinline__ void init(int r) {
        nl.init(r);
        pao = ao + (size_t)r * EDD;
    }
    __device__ __forceinline__ float4 ld4(int c) const {
        if (c < MEMD) return nl.ld4(c);
        return *reinterpret_cast<const float4*>(pao + (c - MEMD));
    }
};
struct ZPairLd {
    const float* Z;
    const float* p0; const float* p1;
    __device__ __forceinline__ void init(int r) {
        p0 = Z + (size_t)r * 100;
        p1 = Z + (size_t)(r + BE) * 100;
    }
    __device__ __forceinline__ float4 ld4(int c) const {
        if (c < 100) return *reinterpret_cast<const float4*>(p0 + c);
        return *reinterpret_cast<const float4*>(p1 + (c - 100));
    }
};

// ---------------- generic fused-gather SGEMM, double-buffered, conflict-free LDS ----------
// C[M,O] = act(A[M,I] @ W[O,I]^T + bias); M % 128 == 0, I % 4 == 0, O % 4 == 0.
// 128x128 tile, BK=16, 256 threads, 8x8 per-thread register tile, packed f32x2 FMA.
// R10 profile showed balanced-pipe limit at 4x8 (LDS 96cyc vs FMA 64cyc per kk/SM);
// 8x8 doubles FMA per fragment byte: LDS 128 vs FMA 128 -> ~1.5x per-FMA throughput.
constexpr int BMT = 128, BNT = 128, BKT = 16;

template <class L>
__global__ __launch_bounds__(256, 2)
void gemm_kernel(L ld, const float* __restrict__ W, const float* __restrict__ bias,
                 float* __restrict__ C, int M, int I, int O, int relu)
{
    __shared__ __align__(16) float As[2][BKT][BMT + 4];   // 132 floats/row (528B, 16B mult)
    __shared__ __align__(16) float Bs[2][BKT][BNT + 4];
    const int t  = threadIdx.x;
    const int tx = t & 15, ty = t >> 4;                   // 16 x 16 thread grid
    const int bm = blockIdx.x * BMT, bn = blockIdx.y * BNT;
    // A load map: 256 threads x two float4 = 128 rows x 16 cols
    const int ar = t >> 1, ac = (t & 1) * 8;
    // B load map: 256 threads x two float4 = 128 rows x 16 cols
    const int br = t >> 1, bc = (t & 1) * 8;
    const bool bvalid = (bn + br) < O;
    const float* wrow = W + (size_t)(bn + br) * I + bc;

    ld.init(bm + ar);                                     // resolve gather row ONCE

    unsigned long long acc2[8][4];   // [row i][g*2+pair]: g=0 -> cols tx*4, g=1 -> cols 64+tx*4
#pragma unroll
    for (int i = 0; i < 8; i++)
#pragma unroll
        for (int j = 0; j < 4; j++) acc2[i][j] = 0ULL;

    const int steps = (I + BKT - 1) / BKT;

    float4 pa0, pa1, pb0, pb1;
    // --- prologue: fetch tile 0 ---
    {
        pa0 = make_float4(0.f, 0.f, 0.f, 0.f); pa1 = pa0;
        if (ac < I)     pa0 = ld.ld4(ac);
        if (ac + 4 < I) pa1 = ld.ld4(ac + 4);
        pb0 = make_float4(0.f, 0.f, 0.f, 0.f); pb1 = pb0;
        if (bvalid) {
            if (bc + 3 < I) pb0 = *reinterpret_cast<const float4*>(wrow);
            if (bc + 7 < I) pb1 = *reinterpret_cast<const float4*>(wrow + 4);
        }
        As[0][ac + 0][ar] = pa0.x; As[0][ac + 1][ar] = pa0.y;
        As[0][ac + 2][ar] = pa0.z; As[0][ac + 3][ar] = pa0.w;
        As[0][ac + 4][ar] = pa1.x; As[0][ac + 5][ar] = pa1.y;
        As[0][ac + 6][ar] = pa1.z; As[0][ac + 7][ar] = pa1.w;
        Bs[0][bc + 0][br] = pb0.x; Bs[0][bc + 1][br] = pb0.y;
        Bs[0][bc + 2][br] = pb0.z; Bs[0][bc + 3][br] = pb0.w;
        Bs[0][bc + 4][br] = pb1.x; Bs[0][bc + 5][br] = pb1.y;
        Bs[0][bc + 6][br] = pb1.z; Bs[0][bc + 7][br] = pb1.w;
    }
    __syncthreads();

    for (int s = 0; s < steps; s++) {
        const int buf = s & 1;
        const bool more = (s + 1) < steps;
        // --- prefetch tile s+1 into registers ---
        if (more) {
            const int k0 = (s + 1) * BKT;
            pa0 = make_float4(0.f, 0.f, 0.f, 0.f); pa1 = pa0;
            if (k0 + ac < I)     pa0 = ld.ld4(k0 + ac);
            if (k0 + ac + 4 < I) pa1 = ld.ld4(k0 + ac + 4);
            pb0 = make_float4(0.f, 0.f, 0.f, 0.f); pb1 = pb0;
            if (bvalid) {
                if (k0 + bc + 3 < I) pb0 = *reinterpret_cast<const float4*>(wrow + k0);
                if (k0 + bc + 7 < I) pb1 = *reinterpret_cast<const float4*>(wrow + k0 + 4);
            }
        }
        // --- compute tile s from SMEM[buf] (conflict-free fragment loads) ---
#pragma unroll
        for (int kk = 0; kk < BKT; kk++) {
            float4 a0 = *reinterpret_cast<const float4*>(&As[buf][kk][ty * 8]);
            float4 a1 = *reinterpret_cast<const float4*>(&As[buf][kk][ty * 8 + 4]);
            ulonglong2 q0 = *reinterpret_cast<const ulonglong2*>(&Bs[buf][kk][tx * 4]);
            ulonglong2 q1 = *reinterpret_cast<const ulonglong2*>(&Bs[buf][kk][64 + tx * 4]);
            float av[8] = {a0.x, a0.y, a0.z, a0.w, a1.x, a1.y, a1.z, a1.w};
#pragma unroll
            for (int i = 0; i < 8; i++) {
                unsigned long long ap = packdup(av[i]);
                fma2(acc2[i][0], ap, q0.x); fma2(acc2[i][1], ap, q0.y);
                fma2(acc2[i][2], ap, q1.x); fma2(acc2[i][3], ap, q1.y);
            }
        }
        // --- store prefetched tile into SMEM[buf^1] ---
        if (more) {
            const int nb = buf ^ 1;
            As[nb][ac + 0][ar] = pa0.x; As[nb][ac + 1][ar] = pa0.y;
            As[nb][ac + 2][ar] = pa0.z; As[nb][ac + 3][ar] = pa0.w;
            As[nb][ac + 4][ar] = pa1.x; As[nb][ac + 5][ar] = pa1.y;
            As[nb][ac + 6][ar] = pa1.z; As[nb][ac + 7][ar] = pa1.w;
            Bs[nb][bc + 0][br] = pb0.x; Bs[nb][bc + 1][br] = pb0.y;
            Bs[nb][bc + 2][br] = pb0.z; Bs[nb][bc + 3][br] = pb0.w;
            Bs[nb][bc + 4][br] = pb1.x; Bs[nb][bc + 5][br] = pb1.y;
            Bs[nb][bc + 6][br] = pb1.z; Bs[nb][bc + 7][br] = pb1.w;
            __syncthreads();
        }
    }

#pragma unroll
    for (int i = 0; i < 8; i++) {
        int row = bm + ty * 8 + i;                        // M % 128 == 0, always valid
        float* crow = C + (size_t)row * O;
#pragma unroll
        for (int g = 0; g < 2; g++) {
            int col = bn + g * 64 + tx * 4;
            if (col < O) {                                // O % 4 == 0 -> group all-or-none
                float x0, x1, x2, x3;
                unpack2(acc2[i][g * 2 + 0], x0, x1);
                unpack2(acc2[i][g * 2 + 1], x2, x3);
                float4 v = make_float4(x0 + bias[col], x1 + bias[col + 1],
                                       x2 + bias[col + 2], x3 + bias[col + 3]);
                if (relu) {
                    v.x = fmaxf(v.x, 0.f); v.y = fmaxf(v.y, 0.f);
                    v.z = fmaxf(v.z, 0.f); v.w = fmaxf(v.w, 0.f);
                }
                *reinterpret_cast<float4*>(crow + col) = v;
            }
        }
    }
}

// ---------------- GRU combine ----------------
__global__ void gru_kernel()
{
    int idx = blockIdx.x * blockDim.x + threadIdx.x;
    if (idx >= BE * MEMD) return;
    int b = idx / MEMD, j = idx - b * MEMD;
    const float* gi = g_GI + (size_t)b * GD;
    float ir = gi[j], iz = gi[172 + j], inn = gi[344 + j];
    {
        const float* gh = g_GH + (size_t)b * GD;
        float h = g_X[(size_t)b * XD + j];
        float r = sigm(ir + gh[j]);
        float z = sigm(iz + gh[172 + j]);
        float n = tanhf(inn + r * gh[344 + j]);
        g_newmem[(size_t)b * MEMD + j] = (1.f - z) * n + z * h;
    }
    {
        const float* gh = g_GH + (size_t)(BE + b) * GD;
        float h = g_X[(size_t)b * XD + 172 + j];
        float r = sigm(ir + gh[j]);
        float z = sigm(iz + gh[172 + j]);
        float n = tanhf(inn + r * gh[344 + j]);
        g_newmem[(size_t)(BE + b) * MEMD + j] = (1.f - z) * n + z * h;
    }
}

// ---------------- scatter priority (last-index-wins: dst over src, high idx wins) ----------------
__global__ void scatter_kernel(const int* __restrict__ src, const int* __restrict__ dst)
{
    int i = blockIdx.x * blockDim.x + threadIdx.x;
    if (i >= NB2) return;
    int node = (i < BE) ? src[i] : dst[i - BE];
    atomicMax(&g_upd[node], i + 1);
}

__global__ void clean_kernel(const int* __restrict__ src, const int* __restrict__ dst)
{
    int i = blockIdx.x * blockDim.x + threadIdx.x;
    if (i >= NB2) return;
    int node = (i < BE) ? src[i] : dst[i - BE];
    g_upd[node] = 0;
}

// ---------------- resolve gather indices once ----------------
__global__ void resolve_nbr_kernel(const int* __restrict__ nid)
{
    int r = blockIdx.x * blockDim.x + threadIdx.x;
    if (r >= NBRROWS) return;
    int node = nid[r];
    int u = g_upd[node];
    g_nridx[r] = (u > 0) ? -u : node;     // negative -> g_newmem row (-v-1)
}

__global__ void resolve_node_kernel(const int* __restrict__ src, const int* __restrict__ dst)
{
    int i = blockIdx.x * blockDim.x + threadIdx.x;
    if (i >= NB2) return;
    int node = (i < BE) ? src[i] : dst[i - BE];
    int u = g_upd[node];
    g_nodeidx[i] = (u > 0) ? -u : node;
}

// ---------------- attention (2 heads x 10 neighbors) -> raw AO ----------------
__global__ void attn_kernel(const float* __restrict__ Q, const float* __restrict__ KV,
                            float* __restrict__ AO)
{
    int m = blockIdx.x;
    __shared__ float qs[EDD];
    __shared__ float att[2][KN];
    int t = threadIdx.x;
    if (t < EDD) qs[t] = Q[(size_t)m * EDD + t];
    __syncthreads();
    if (t < 2 * KN) {
        int h = t / KN, k = t - h * KN;
        const float* kr = KV + (size_t)(m * KN + k) * 200 + h * 50;
        const float* qh = qs + h * 50;
        float s = 0.f;
#pragma unroll 10
        for (int j = 0; j < 50; j++) s += qh[j] * kr[j];
        att[h][k] = s * 0.14142135623730951f;   // 1/sqrt(50)
    }
    __syncthreads();
    if (t < 2) {
        float mx = -1e30f;
        for (int k = 0; k < KN; k++) mx = fmaxf(mx, att[t][k]);
        float e[KN]; float sum = 0.f;
        for (int k = 0; k < KN; k++) { e[k] = expf(att[t][k] - mx); sum += e[k]; }
        float inv = 1.f / sum;
        for (int k = 0; k < KN; k++) att[t][k] = e[k] * inv;
    }
    __syncthreads();
    if (t < EDD) {
        int h = t / 50;
        float s = 0.f;
#pragma unroll
        for (int k = 0; k < KN; k++)
            s += att[h][k] * KV[(size_t)(m * KN + k) * 200 + 100 + t];
        AO[(size_t)m * EDD + t] = s;
    }
}

// ---------------- final score ----------------
__global__ void score_kernel(const float* __restrict__ H1F, const float* __restrict__ pW2,
                             const float* __restrict__ pb2, float* __restrict__ out)
{
    int warp = (blockIdx.x * blockDim.x + threadIdx.x) >> 5;
    int lane = threadIdx.x & 31;
    if (warp >= BE) return;
    const float* h = H1F + (size_t)warp * HIDD;
    float s = 0.f;
#pragma unroll
    for (int j = lane; j < HIDD; j += 32) s += h[j] * pW2[j];
#pragma unroll
    for (int o = 16; o > 0; o >>= 1) s += __shfl_xor_sync(0xffffffffu, s, o);
    if (lane == 0) out[warp] = 1.f / (1.f + expf(-(s + pb2[0])));
}

// ---------------- host-side ----------------
template <class L>
static void run_gemm(const L& ld, const float* W, const float* b, float* C,
                     int M, int I, int O, int relu)
{
    dim3 grid(M / BMT, (O + BNT - 1) / BNT);
    gemm_kernel<L><<<grid, 256>>>(ld, W, b, C, M, I, O, relu);
}

extern "C" void kernel_launch(void* const* d_in, const int* in_sizes, int n_in,
                              void* d_out, int out_size)
{
    (void)in_sizes; (void)n_in; (void)out_size;
    const float* memory  = (const float*)d_in[0];
    const int*   src     = (const int*)  d_in[1];
    const int*   dst     = (const int*)  d_in[2];
    const float* dt      = (const float*)d_in[3];
    const int*   nids    = (const int*)  d_in[4];
    const float* ndt     = (const float*)d_in[5];
    const float* t_w     = (const float*)d_in[6];
    const float* t_b     = (const float*)d_in[7];
    const float* m_W1    = (const float*)d_in[8];
    const float* m_b1    = (const float*)d_in[9];
    const float* m_W2    = (const float*)d_in[10];
    const float* m_b2    = (const float*)d_in[11];
    const float* g_Wih   = (const float*)d_in[12];
    const float* g_Whh   = (const float*)d_in[13];
    const float* g_bih   = (const float*)d_in[14];
    const float* g_bhh   = (const float*)d_in[15];
    const float* k_W     = (const float*)d_in[16];
    const float* k_b     = (const float*)d_in[17];
    const float* v_W     = (const float*)d_in[18];
    const float* v_b     = (const float*)d_in[19];
    const float* q_W     = (const float*)d_in[20];
    const float* q_b     = (const float*)d_in[21];
    const float* in_W    = (const float*)d_in[22];
    const float* in_b    = (const float*)d_in[23];
    const float* o_W     = (const float*)d_in[24];
    const float* o_b     = (const float*)d_in[25];
    const float* c_W     = (const float*)d_in[26];
    const float* c_b     = (const float*)d_in[27];
    const float* p_W1    = (const float*)d_in[28];
    const float* p_b1    = (const float*)d_in[29];
    const float* p_W2    = (const float*)d_in[30];
    const float* p_b2    = (const float*)d_in[31];
    float* out = (float*)d_out;

    float *dX, *dH1, *dRAW, *dGI, *dGH, *dNM, *dQ, *dKV, *dAO, *dZ, *dH1F;
    float *dCWkv, *dCWq, *dCWc, *dcb;
    int *dUPD, *dNRI, *dNI;
    cudaGetSymbolAddress((void**)&dX,    g_X);
    cudaGetSymbolAddress((void**)&dH1,   g_H1);
    cudaGetSymbolAddress((void**)&dRAW,  g_RAW);
    cudaGetSymbolAddress((void**)&dGI,   g_GI);
    cudaGetSymbolAddress((void**)&dGH,   g_GH);
    cudaGetSymbolAddress((void**)&dNM,   g_newmem);
    cudaGetSymbolAddress((void**)&dUPD,  g_upd);
    cudaGetSymbolAddress((void**)&dNRI,  g_nridx);
    cudaGetSymbolAddress((void**)&dNI,   g_nodeidx);
    cudaGetSymbolAddress((void**)&dQ,    g_Q);
    cudaGetSymbolAddress((void**)&dKV,   g_KV);
    cudaGetSymbolAddress((void**)&dAO,   g_AO);
    cudaGetSymbolAddress((void**)&dZ,    g_Z);
    cudaGetSymbolAddress((void**)&dH1F,  g_H1F);
    cudaGetSymbolAddress((void**)&dCWkv, g_CWkv);
    cudaGetSymbolAddress((void**)&dCWq,  g_CWq);
    cudaGetSymbolAddress((void**)&dCWc,  g_CWc);
    cudaGetSymbolAddress((void**)&dcb,   g_cb);

    // 1) fused weight precompute (single merged launch)
    prepw_kernel<<<(PREPW_TOTAL + 255) / 256, 256>>>(in_W, in_b, k_W, k_b, v_W, v_b,
                                                     q_W, q_b, c_W, c_b, o_W, o_b);

    // 2) X = [s_src | s_dst | time_enc(dt)]
    prepx_kernel<<<BE, 128>>>(memory, src, dst, dt, t_w, t_b);

    // 3) message MLP
    run_gemm(DenseLd{dX, XD, 0},    m_W1, m_b1, dH1,  BE, XD,   MSGD, 1);
    run_gemm(DenseLd{dH1, MSGD, 0}, m_W2, m_b2, dRAW, BE, MSGD, MSGD, 0);

    // 4) GRU gates: gi (shared) + gh (src/dst fused into one M=2B GEMM)
    run_gemm(DenseLd{dRAW, MSGD, 0}, g_Wih, g_bih, dGI, BE,  MSGD, GD, 0);
    run_gemm(GHLd{dX},               g_Whh, g_bhh, dGH, NB2, MEMD, GD, 0);
    gru_kernel<<<(BE * MEMD + 255) / 256, 256>>>();

    // 5) scatter winners + resolve gather indices once
    scatter_kernel<<<NB2 / 256, 256>>>(src, dst);
    resolve_nbr_kernel <<<NBRROWS / 256, 256>>>(nids);
    resolve_node_kernel<<<NB2 / 256, 256>>>(src, dst);

    // 6) attention projections on updated memory (fused in_W weights)
    NodeLd nodeld{memory, dNM, dNI};
    run_gemm(nodeld, dCWq, dcb + 200, dQ, NB2, MEMD, EDD, 0);
    run_gemm(NbrLd{memory, dNM, dNRI, ndt, t_w, t_b},
             dCWkv, dcb, dKV, NBRROWS, 272, 200, 0);

    // 7) softmax attention
    attn_kernel<<<NB2, 128>>>(dQ, dKV, dAO);

    // 8) z = relu([node_mem | ao_raw] @ CWc^T + cbc)   (o_W folded)
    run_gemm(NodeAOLd{nodeld, dAO}, dCWc, dcb + 300, dZ, NB2, 272, MSGD, 1);

    // 9) link predictor
    run_gemm(ZPairLd{dZ}, p_W1, p_b1, dH1F, BE, 200, HIDD, 1);
    score_kernel<<<(BE * 32 + 255) / 256, 256>>>(dH1F, p_W2, p_b2, out);

    // 10) restore upd[] for deterministic graph replay
    clean_kernel<<<NB2 / 256, 256>>>(src, dst);
}